// round 11
// baseline (speedup 1.0000x reference)
#include <cuda_runtime.h>
#include <math.h>

#define BB 32
#define LL 4096
#define CC 256
#define VV 5
#define THR 128
#define GXB 16          // blocks per batch for kstat & kbig (256 tokens each)

// ---------------- device scratch ----------------
__device__ __align__(16) float g_base[BB * CC];
__device__ __align__(16) float g_A1[BB * VV * CC];    // sum_l a*rs*(f-m)
__device__ __align__(16) float g_A3[BB * VV];         // sum_l a
__device__ __align__(16) float g_projg[BB * VV * CC];
__device__ __align__(16) float g_sgp[BB * VV];
__device__ __align__(16) float g_sbp[BB * VV];
__device__ __align__(16) float g_MT[CC * CC];         // MT[e][c] = sum_k Wk[e,k]*Wq[c,k]
__device__ __align__(16) float4 g_mrs4[BB * LL / 2];  // (m0,rs0,m1,rs1) per token pair
__device__ unsigned g_cnt[BB];

// ---------------- kstat tail smem overlay (56 KB) ----------------
#define T_SL(sm)  ((float*)(sm))                 // [5][256]
#define T_X(sm)   ((float*)((sm) + 5120))        // [5][256]
#define T_P(sm)   ((float*)((sm) + 30720))       // [2][5][256]
#define T_PR(sm)  ((float*)((sm) + 51200))       // [5][256]
#define TAIL_BYTES 56320

// ---------------- kslot smem overlay (115 KB, 1024 threads) ----------------
#define KS_SL(sm)  ((float*)(sm))                // [5][256]   5120
#define KS_X(sm)   ((float*)((sm) + 5120))       // [5][256]
#define KS_U(sm)   ((float*)((sm) + 10240))      // [5][256]
#define KS_H(sm)   ((float*)((sm) + 15360))      // [5][256]
#define KS_HID(sm) ((float*)((sm) + 20480))      // [5][512]  10240
#define KS_P(sm)   ((float*)((sm) + 30720))      // up to [16][5][256] = 81920
#define KS_PR(sm)  ((float*)((sm) + 112640))     // [5][256]
#define KSLOT_BYTES 117760

// ---------------- 128-thread helpers (kstat tail only) ----------------
__device__ __forceinline__ void ln_rows128(const float* __restrict__ src,
                                           float* __restrict__ dst,
                                           const float* __restrict__ gc,
                                           const float* __restrict__ bc, int t) {
    int wid = t >> 5, lane = t & 31;
    for (int v = wid; v < VV; v += 4) {
        float x[8], s = 0.f, q = 0.f;
#pragma unroll
        for (int i = 0; i < 8; i++) {
            x[i] = src[v * CC + lane + 32 * i];
            s += x[i]; q += x[i] * x[i];
        }
#pragma unroll
        for (int off = 16; off; off >>= 1) {
            s += __shfl_xor_sync(0xffffffffu, s, off);
            q += __shfl_xor_sync(0xffffffffu, q, off);
        }
        float m = s * (1.0f / 256.0f);
        float rs = rsqrtf(q * (1.0f / 256.0f) - m * m + 1e-5f);
#pragma unroll
        for (int i = 0; i < 8; i++) {
            int c = lane + 32 * i;
            dst[v * CC + c] = (x[i] - m) * rs * gc[c] + bc[c];
        }
    }
}

// out 256, depth 256; 2-way k-split over 128 threads (kstat tail only)
__device__ __forceinline__ void gemm256_128(const float* __restrict__ sIn,
                                            const float* __restrict__ W,
                                            float* __restrict__ sP, int t) {
    int grp = t & 63, seg = t >> 6;
    const float4* Wp = (const float4*)W + seg * 128 * 64 + grp;
    const float* xin = sIn + seg * 128;
    float4 acc[VV];
#pragma unroll
    for (int v = 0; v < VV; v++) acc[v] = make_float4(0.f, 0.f, 0.f, 0.f);
#pragma unroll 8
    for (int k = 0; k < 128; k++) {
        float4 w = Wp[k * 64];
#pragma unroll
        for (int v = 0; v < VV; v++) {
            float xa = xin[v * CC + k];
            acc[v].x += xa * w.x; acc[v].y += xa * w.y;
            acc[v].z += xa * w.z; acc[v].w += xa * w.w;
        }
    }
#pragma unroll
    for (int v = 0; v < VV; v++)
        ((float4*)(sP + (seg * VV + v) * CC))[grp] = acc[v];
}

// kstat's LN(slots) -> projection (128 threads). Requires T_SL filled.
__device__ void ln_proj_tail128(char* sm, int t, int b,
                                const float* g_sl, const float* b_sl,
                                const float* g_in, const float* b_in, float scale) {
    float* sSl = T_SL(sm); float* sX = T_X(sm);
    float* sP = T_P(sm);   float* sPR = T_PR(sm);
    ln_rows128(sSl, sX, g_sl, b_sl, t);
    __syncthreads();
    gemm256_128(sX, g_MT, sP, t);
    __syncthreads();
    for (int idx = t; idx < VV * CC; idx += THR) {
        int v = idx >> 8, c = idx & 255;
        float pr = (sP[v * CC + c] + sP[(VV + v) * CC + c]) * scale;
        g_projg[b * VV * CC + idx] = g_in[c] * pr;
        sPR[idx] = pr;
    }
    __syncthreads();
    if (t < 10) {
        int v = t % 5;
        const float* coef = (t < 5) ? g_in : b_in;
        float s = 0.f;
#pragma unroll 8
        for (int c = 0; c < CC; c++) s += coef[c] * sPR[v * CC + c];
        if (t < 5) g_sgp[b * VV + v] = s; else g_sbp[b * VV + v] = s;
    }
}

// ---------------- km: MT = Wk @ Wq^T + zero all scratch ----------------
__global__ void __launch_bounds__(256) km(const float* __restrict__ Wq,
                                          const float* __restrict__ Wk) {
    __shared__ float As[32][33];
    __shared__ float Bs[32][33];
    int tx = threadIdx.x & 31, ty = threadIdx.x >> 5;
    int c0 = blockIdx.x * 32, e0 = blockIdx.y * 32;

    int flat = (blockIdx.y * 8 + blockIdx.x) * 256 + threadIdx.x;  // 0..16383
    for (int i = flat; i < BB * VV * CC; i += 16384) g_A1[i] = 0.f;
    if (flat < BB * CC) g_base[flat] = 0.f;
    if (flat < BB * VV) g_A3[flat] = 0.f;
    if (flat < BB) g_cnt[flat] = 0u;

    float acc[4] = {0.f, 0.f, 0.f, 0.f};
    for (int k0 = 0; k0 < CC; k0 += 32) {
#pragma unroll
        for (int j = 0; j < 4; j++) {
            As[ty + 8 * j][tx] = Wk[(e0 + ty + 8 * j) * CC + k0 + tx];
            Bs[ty + 8 * j][tx] = Wq[(c0 + ty + 8 * j) * CC + k0 + tx];
        }
        __syncthreads();
#pragma unroll
        for (int kk = 0; kk < 32; kk++) {
            float bq = Bs[tx][kk];
#pragma unroll
            for (int j = 0; j < 4; j++) acc[j] += As[ty + 8 * j][kk] * bq;
        }
        __syncthreads();
    }
#pragma unroll
    for (int j = 0; j < 4; j++)
        g_MT[(e0 + ty + 8 * j) * CC + c0 + tx] = acc[j];
}

// ---------------- kstat: per-token (m, rs) + g_base column sums; init tail ----------------
__global__ void __launch_bounds__(128) kstat(const float* __restrict__ F,
                                             const float* __restrict__ noise,
                                             float* __restrict__ slots,
                                             const float* __restrict__ g_in,
                                             const float* __restrict__ b_in,
                                             const float* __restrict__ g_sl,
                                             const float* __restrict__ b_sl,
                                             const float* __restrict__ scale_p,
                                             const float* __restrict__ ns_p) {
    extern __shared__ char sm[];
    __shared__ unsigned flg;
    int b = blockIdx.y, t = threadIdx.x;
    int w = t >> 5, lane = t & 31;
    int l0 = blockIdx.x * 256 + w * 64;
    const float4* base = (const float4*)(F + ((size_t)(b * LL + l0)) * CC);

    float cs[8] = {0.f, 0.f, 0.f, 0.f, 0.f, 0.f, 0.f, 0.f};

    for (int r = 0; r < 64; r += 2) {
        float4 fa0 = base[r * 64 + lane];
        float4 fb0 = base[r * 64 + 32 + lane];
        float4 fa1 = base[r * 64 + 64 + lane];
        float4 fb1 = base[r * 64 + 96 + lane];
        float s0 = (fa0.x + fa0.y) + (fa0.z + fa0.w) + (fb0.x + fb0.y) + (fb0.z + fb0.w);
        float q0 = fa0.x * fa0.x + fa0.y * fa0.y + fa0.z * fa0.z + fa0.w * fa0.w
                 + fb0.x * fb0.x + fb0.y * fb0.y + fb0.z * fb0.z + fb0.w * fb0.w;
        float s1 = (fa1.x + fa1.y) + (fa1.z + fa1.w) + (fb1.x + fb1.y) + (fb1.z + fb1.w);
        float q1 = fa1.x * fa1.x + fa1.y * fa1.y + fa1.z * fa1.z + fa1.w * fa1.w
                 + fb1.x * fb1.x + fb1.y * fb1.y + fb1.z * fb1.z + fb1.w * fb1.w;
        cs[0] += fa0.x + fa1.x; cs[1] += fa0.y + fa1.y;
        cs[2] += fa0.z + fa1.z; cs[3] += fa0.w + fa1.w;
        cs[4] += fb0.x + fb1.x; cs[5] += fb0.y + fb1.y;
        cs[6] += fb0.z + fb1.z; cs[7] += fb0.w + fb1.w;
#pragma unroll
        for (int off = 16; off; off >>= 1) {
            s0 += __shfl_xor_sync(0xffffffffu, s0, off);
            s1 += __shfl_xor_sync(0xffffffffu, s1, off);
            q0 += __shfl_xor_sync(0xffffffffu, q0, off);
            q1 += __shfl_xor_sync(0xffffffffu, q1, off);
        }
        float m0 = s0 * (1.0f / 256.0f);
        float m1 = s1 * (1.0f / 256.0f);
        float rs0 = rsqrtf(q0 * (1.0f / 256.0f) - m0 * m0 + 1e-5f);
        float rs1 = rsqrtf(q1 * (1.0f / 256.0f) - m1 * m1 + 1e-5f);
        if (lane == 0)
            g_mrs4[((size_t)b * LL + l0 + r) >> 1] = make_float4(m0, rs0, m1, rs1);
    }

    int cA = 4 * lane, cB = 128 + 4 * lane;
#pragma unroll
    for (int i = 0; i < 4; i++) {
        atomicAdd(&g_base[b * CC + cA + i], cs[i]);
        atomicAdd(&g_base[b * CC + cB + i], cs[4 + i]);
    }
    __threadfence();
    __syncthreads();   // ALL threads' atomics done+fenced before counter bump
    if (t == 0) flg = atomicAdd(&g_cnt[b], 1u);
    __syncthreads();
    if (flg != GXB - 1) return;

    // init slots = mean + noise*|ns|, then projection
    float* sSl = T_SL(sm);
    float ns = fabsf(ns_p[0]);
    for (int idx = t; idx < VV * CC; idx += THR) {
        int c = idx & 255;
        float sv = __ldcg(&g_base[b * CC + c]) * (1.0f / (float)LL)
                 + noise[b * VV * CC + idx] * ns;
        sSl[idx] = sv;
        slots[b * VV * CC + idx] = sv;
    }
    __syncthreads();
    ln_proj_tail128(sm, t, b, g_sl, b_sl, g_in, b_in, scale_p[0]);
    if (t == 0) g_cnt[b] = 0;
}

// ---------------- kbig: streaming only — no tail, no counters, no dynamic smem ----------------
__global__ void __launch_bounds__(128) kbig(const float* __restrict__ F,
                                            float* __restrict__ attn,
                                            int write_attn) {
    int b = blockIdx.y, t = threadIdx.x;
    int w = t >> 5, lane = t & 31;
    int l0 = blockIdx.x * 256 + w * 64;
    int cA = 4 * lane, cB = 128 + 4 * lane;

    float gp[VV][8], sgp[VV], sbp[VV];
#pragma unroll
    for (int v = 0; v < VV; v++) {
        sgp[v] = g_sgp[b * VV + v];
        sbp[v] = g_sbp[b * VV + v];
        const float* gpp = &g_projg[(b * VV + v) * CC];
#pragma unroll
        for (int i = 0; i < 8; i++)
            gp[v][i] = gpp[(i < 4) ? (cA + i) : (cB + (i - 4))];
    }
    float A1[VV][8], A3[VV];
#pragma unroll
    for (int v = 0; v < VV; v++) {
        A3[v] = 0.f;
#pragma unroll
        for (int i = 0; i < 8; i++) A1[v][i] = 0.f;
    }

    const float4* base = (const float4*)(F + ((size_t)(b * LL + l0)) * CC);
    float* aout = attn + ((size_t)b * LL + l0) * VV;

    for (int r = 0; r < 64; r += 2) {
        float4 fa0 = base[r * 64 + lane];
        float4 fb0 = base[r * 64 + 32 + lane];
        float4 fa1 = base[r * 64 + 64 + lane];
        float4 fb1 = base[r * 64 + 96 + lane];
        float f0[8] = {fa0.x, fa0.y, fa0.z, fa0.w, fb0.x, fb0.y, fb0.z, fb0.w};
        float f1[8] = {fa1.x, fa1.y, fa1.z, fa1.w, fb1.x, fb1.y, fb1.z, fb1.w};

        float d0[VV] = {0, 0, 0, 0, 0}, d1[VV] = {0, 0, 0, 0, 0};
#pragma unroll
        for (int i = 0; i < 8; i++) {
            float x0 = f0[i], x1 = f1[i];
#pragma unroll
            for (int v = 0; v < VV; v++) {
                d0[v] += x0 * gp[v][i];
                d1[v] += x1 * gp[v][i];
            }
        }
#pragma unroll
        for (int off = 16; off; off >>= 1) {
#pragma unroll
            for (int v = 0; v < VV; v++) {
                d0[v] += __shfl_xor_sync(0xffffffffu, d0[v], off);
                d1[v] += __shfl_xor_sync(0xffffffffu, d1[v], off);
            }
        }
        float4 mr = g_mrs4[((size_t)b * LL + l0 + r) >> 1];
        float m0 = mr.x, rs0 = mr.y, m1 = mr.z, rs1 = mr.w;

        float lg0[VV], lg1[VV];
#pragma unroll
        for (int v = 0; v < VV; v++) {
            lg0[v] = rs0 * (d0[v] - m0 * sgp[v]) + sbp[v];
            lg1[v] = rs1 * (d1[v] - m1 * sgp[v]) + sbp[v];
        }
        float mx0 = lg0[0], mx1 = lg1[0];
#pragma unroll
        for (int v = 1; v < VV; v++) {
            mx0 = fmaxf(mx0, lg0[v]);
            mx1 = fmaxf(mx1, lg1[v]);
        }
        float e0[VV], e1[VV], se0 = 0.f, se1 = 0.f;
#pragma unroll
        for (int v = 0; v < VV; v++) {
            e0[v] = __expf(lg0[v] - mx0); se0 += e0[v];
            e1[v] = __expf(lg1[v] - mx1); se1 += e1[v];
        }
        float inv0 = 1.0f / se0, inv1 = 1.0f / se1;
        float a0[VV], a1v[VV];
#pragma unroll
        for (int v = 0; v < VV; v++) {
            a0[v] = e0[v] * inv0;
            a1v[v] = e1[v] * inv1;
        }

#pragma unroll
        for (int i = 0; i < 8; i++) { f0[i] -= m0; f1[i] -= m1; }
#pragma unroll
        for (int v = 0; v < VV; v++) {
            float c0 = a0[v] * rs0, c1 = a1v[v] * rs1;
            A3[v] += a0[v] + a1v[v];
#pragma unroll
            for (int i = 0; i < 8; i++)
                A1[v][i] += c0 * f0[i] + c1 * f1[i];
        }

        if (write_attn) {
            if (lane < VV) {
                float av = lane == 0 ? a0[0] : lane == 1 ? a0[1] : lane == 2 ? a0[2]
                         : lane == 3 ? a0[3] : a0[4];
                aout[r * VV + lane] = av;
            } else if (lane < 2 * VV) {
                int j = lane - VV;
                float av = j == 0 ? a1v[0] : j == 1 ? a1v[1] : j == 2 ? a1v[2]
                         : j == 3 ? a1v[3] : a1v[4];
                aout[(r + 1) * VV + j] = av;
            }
        }
    }

    // flush block contributions (coalesced REDG per v-plane)
#pragma unroll
    for (int v = 0; v < VV; v++) {
#pragma unroll
        for (int i = 0; i < 8; i++) {
            int c = (i < 4) ? (cA + i) : (cB + (i - 4));
            atomicAdd(&g_A1[(b * VV + v) * CC + c], A1[v][i]);
        }
        if (lane == 0) atomicAdd(&g_A3[b * VV + v], A3[v]);
    }
}

// ---------------- kslot: slot update, 1024 threads, deep k-split GEMMs ----------------
__global__ void __launch_bounds__(1024) kslot(float* __restrict__ slots,
                                              const float* __restrict__ g_in,
                                              const float* __restrict__ b_in,
                                              const float* __restrict__ g_sl,
                                              const float* __restrict__ b_sl,
                                              const float* __restrict__ g_up,
                                              const float* __restrict__ b_up,
                                              const float* __restrict__ Wv,
                                              const float* __restrict__ W1,
                                              const float* __restrict__ b1,
                                              const float* __restrict__ W2,
                                              const float* __restrict__ b2,
                                              const float* __restrict__ scale_p,
                                              int do_proj) {
    extern __shared__ char sm[];
    __shared__ float s_a3[VV];
    float* sSl = KS_SL(sm); float* sX = KS_X(sm); float* sU = KS_U(sm);
    float* sH = KS_H(sm);   float* sHid = KS_HID(sm);
    float* sP = KS_P(sm);   float* sPR = KS_PR(sm);

    int b = blockIdx.x, t = threadIdx.x;
    int wid = t >> 5, lane = t & 31;

    if (t < VV) { s_a3[t] = __ldcg(&g_A3[b * VV + t]); g_A3[b * VV + t] = 0.f; }
    for (int idx = t; idx < VV * CC; idx += 1024)
        sSl[idx] = slots[b * VV * CC + idx];
    __syncthreads();
    for (int idx = t; idx < VV * CC; idx += 1024) {
        int v = idx >> 8, c = idx & 255;
        float a1 = __ldcg(&g_A1[b * VV * CC + idx]);
        g_A1[b * VV * CC + idx] = 0.f;
        sX[idx] = g_in[c] * a1 + b_in[c] * s_a3[v];
    }
    __syncthreads();

    // ---- Wv GEMM: 64 f4-groups x 16 segs (depth 16) ----
    {
        int grp = t & 63, seg = t >> 6;
        const float4* Wp = (const float4*)Wv + (seg * 16) * 64 + grp;
        const float* xin = sX + seg * 16;
        float4 acc[VV];
#pragma unroll
        for (int v = 0; v < VV; v++) acc[v] = make_float4(0.f, 0.f, 0.f, 0.f);
#pragma unroll
        for (int k = 0; k < 16; k++) {
            float4 wv4 = Wp[k * 64];
#pragma unroll
            for (int v = 0; v < VV; v++) {
                float xa = xin[v * CC + k];
                acc[v].x += xa * wv4.x; acc[v].y += xa * wv4.y;
                acc[v].z += xa * wv4.z; acc[v].w += xa * wv4.w;
            }
        }
#pragma unroll
        for (int v = 0; v < VV; v++)
            ((float4*)(sP + (seg * VV + v) * CC))[grp] = acc[v];
    }
    __syncthreads();
    for (int idx = t; idx < VV * CC; idx += 1024) {
        int v = idx >> 8, c = idx & 255;
        float s = 0.f;
#pragma unroll
        for (int sg = 0; sg < 16; sg++) s += sP[(sg * VV + v) * CC + c];
        sU[idx] = s / (s_a3[v] + 1e-8f);
    }
    __syncthreads();

    // ---- LN(updates) -> sH (warps 0..4, one slot each) ----
    if (wid < VV) {
        float x[8], s = 0.f, q = 0.f;
#pragma unroll
        for (int i = 0; i < 8; i++) {
            x[i] = sU[wid * CC + lane + 32 * i];
            s += x[i]; q += x[i] * x[i];
        }
#pragma unroll
        for (int off = 16; off; off >>= 1) {
            s += __shfl_xor_sync(0xffffffffu, s, off);
            q += __shfl_xor_sync(0xffffffffu, q, off);
        }
        float m = s * (1.0f / 256.0f);
        float rs = rsqrtf(q * (1.0f / 256.0f) - m * m + 1e-5f);
#pragma unroll
        for (int i = 0; i < 8; i++) {
            int c = lane + 32 * i;
            sH[wid * CC + c] = (x[i] - m) * rs * g_up[c] + b_up[c];
        }
    }
    __syncthreads();

    // ---- W1 GEMM: 128 f4-groups x 8 segs (depth 32) ----
    {
        int grp = t & 127, seg = t >> 7;
        const float4* Wp = (const float4*)W1 + (seg * 32) * 128 + grp;
        const float* xin = sH + seg * 32;
        float4 acc[VV];
#pragma unroll
        for (int v = 0; v < VV; v++) acc[v] = make_float4(0.f, 0.f, 0.f, 0.f);
#pragma unroll 8
        for (int k = 0; k < 32; k++) {
            float4 wv4 = Wp[k * 128];
#pragma unroll
            for (int v = 0; v < VV; v++) {
                float xa = xin[v * CC + k];
                acc[v].x += xa * wv4.x; acc[v].y += xa * wv4.y;
                acc[v].z += xa * wv4.z; acc[v].w += xa * wv4.w;
            }
        }
#pragma unroll
        for (int v = 0; v < VV; v++)
            ((float4*)(sP + (seg * VV + v) * 512))[grp] = acc[v];
    }
    __syncthreads();
    for (int idx = t; idx < VV * 512; idx += 1024) {
        int v = idx >> 9, j = idx & 511;
        float h = b1[j];
#pragma unroll
        for (int sg = 0; sg < 8; sg++) h += sP[(sg * VV + v) * 512 + j];
        sHid[idx] = fmaxf(h, 0.f);
    }
    __syncthreads();

    // ---- W2 GEMM: 64 f4-groups x 16 segs (depth 32) ----
    {
        int grp = t & 63, seg = t >> 6;
        const float4* Wp = (const float4*)W2 + (seg * 32) * 64 + grp;
        const float* xin = sHid + seg * 32;
        float4 acc[VV];
#pragma unroll
        for (int v = 0; v < VV; v++) acc[v] = make_float4(0.f, 0.f, 0.f, 0.f);
#pragma unroll 8
        for (int k = 0; k < 32; k++) {
            float4 wv4 = Wp[k * 64];
#pragma unroll
            for (int v = 0; v < VV; v++) {
                float xa = xin[v * 512 + k];
                acc[v].x += xa * wv4.x; acc[v].y += xa * wv4.y;
                acc[v].z += xa * wv4.z; acc[v].w += xa * wv4.w;
            }
        }
#pragma unroll
        for (int v = 0; v < VV; v++)
            ((float4*)(sP + (seg * VV + v) * CC))[grp] = acc[v];
    }
    __syncthreads();
    for (int idx = t; idx < VV * CC; idx += 1024) {
        int v = idx >> 8, c = idx & 255;
        float d = b2[c];
#pragma unroll
        for (int sg = 0; sg < 16; sg++) d += sP[(sg * VV + v) * CC + c];
        float sn = sSl[idx] + d;
        sSl[idx] = sn;
        slots[b * VV * CC + idx] = sn;
    }
    __syncthreads();

    if (!do_proj) return;

    // ---- LN(slots) -> sX ----
    if (wid < VV) {
        float x[8], s = 0.f, q = 0.f;
#pragma unroll
        for (int i = 0; i < 8; i++) {
            x[i] = sSl[wid * CC + lane + 32 * i];
            s += x[i]; q += x[i] * x[i];
        }
#pragma unroll
        for (int off = 16; off; off >>= 1) {
            s += __shfl_xor_sync(0xffffffffu, s, off);
            q += __shfl_xor_sync(0xffffffffu, q, off);
        }
        float m = s * (1.0f / 256.0f);
        float rs = rsqrtf(q * (1.0f / 256.0f) - m * m + 1e-5f);
#pragma unroll
        for (int i = 0; i < 8; i++) {
            int c = lane + 32 * i;
            sX[wid * CC + c] = (x[i] - m) * rs * g_sl[c] + b_sl[c];
        }
    }
    __syncthreads();

    // ---- MT GEMM (same shape as Wv) ----
    {
        int grp = t & 63, seg = t >> 6;
        const float4* Wp = (const float4*)g_MT + (seg * 16) * 64 + grp;
        const float* xin = sX + seg * 16;
        float4 acc[VV];
#pragma unroll
        for (int v = 0; v < VV; v++) acc[v] = make_float4(0.f, 0.f, 0.f, 0.f);
#pragma unroll
        for (int k = 0; k < 16; k++) {
            float4 wv4 = Wp[k * 64];
#pragma unroll
            for (int v = 0; v < VV; v++) {
                float xa = xin[v * CC + k];
                acc[v].x += xa * wv4.x; acc[v].y += xa * wv4.y;
                acc[v].z += xa * wv4.z; acc[v].w += xa * wv4.w;
            }
        }
#pragma unroll
        for (int v = 0; v < VV; v++)
            ((float4*)(sP + (seg * VV + v) * CC))[grp] = acc[v];
    }
    __syncthreads();
    float sc = scale_p[0];
    for (int idx = t; idx < VV * CC; idx += 1024) {
        int v = idx >> 8, c = idx & 255;
        float s = 0.f;
#pragma unroll
        for (int sg = 0; sg < 16; sg++) s += sP[(sg * VV + v) * CC + c];
        float pr = s * sc;
        g_projg[b * VV * CC + idx] = g_in[c] * pr;
        sPR[idx] = pr;
    }
    __syncthreads();
    if (t < 10) {
        int v = t % 5;
        const float* coef = (t < 5) ? g_in : b_in;
        float s = 0.f;
#pragma unroll 8
        for (int c = 0; c < CC; c++) s += coef[c] * sPR[v * CC + c];
        if (t < 5) g_sgp[b * VV + v] = s; else g_sbp[b * VV + v] = s;
    }
}

// ---------------- host ----------------
extern "C" void kernel_launch(void* const* d_in, const int* in_sizes, int n_in,
                              void* d_out, int out_size) {
    const float* F     = (const float*)d_in[0];
    const float* noise = (const float*)d_in[1];
    const float* Wq    = (const float*)d_in[2];
    const float* Wk    = (const float*)d_in[3];
    const float* Wv    = (const float*)d_in[4];
    const float* scale = (const float*)d_in[5];
    const float* g_in  = (const float*)d_in[6];
    const float* b_in  = (const float*)d_in[7];
    const float* g_sl  = (const float*)d_in[8];
    const float* b_sl  = (const float*)d_in[9];
    const float* g_up  = (const float*)d_in[10];
    const float* b_up  = (const float*)d_in[11];
    const float* W1    = (const float*)d_in[12];
    const float* b1    = (const float*)d_in[13];
    const float* W2    = (const float*)d_in[14];
    const float* b2    = (const float*)d_in[15];
    const float* nsc   = (const float*)d_in[16];

    float* out       = (float*)d_out;
    float* slots_out = out;                    // [B,V,C]
    float* attn_out  = out + BB * VV * CC;     // [B,L,V]

    cudaFuncSetAttribute(kstat, cudaFuncAttributeMaxDynamicSharedMemorySize, TAIL_BYTES);
    cudaFuncSetAttribute(kslot, cudaFuncAttributeMaxDynamicSharedMemorySize, KSLOT_BYTES);

    km<<<dim3(8, 8), 256>>>(Wq, Wk);
    kstat<<<dim3(GXB, 32), THR, TAIL_BYTES>>>(F, noise, slots_out, g_in, b_in,
                                              g_sl, b_sl, scale, nsc);

    kbig<<<dim3(GXB, 32), THR>>>(F, attn_out, 0);
    kslot<<<BB, 1024, KSLOT_BYTES>>>(slots_out, g_in, b_in, g_sl, b_sl, g_up, b_up,
                                     Wv, W1, b1, W2, b2, scale, 1);
    kbig<<<dim3(GXB, 32), THR>>>(F, attn_out, 0);
    kslot<<<BB, 1024, KSLOT_BYTES>>>(slots_out, g_in, b_in, g_sl, b_sl, g_up, b_up,
                                     Wv, W1, b1, W2, b2, scale, 1);
    kbig<<<dim3(GXB, 32), THR>>>(F, attn_out, 1);
    kslot<<<BB, 1024, KSLOT_BYTES>>>(slots_out, g_in, b_in, g_sl, b_sl, g_up, b_up,
                                     Wv, W1, b1, W2, b2, scale, 0);
}

// round 12
// speedup vs baseline: 1.0459x; 1.0459x over previous
#include <cuda_runtime.h>
#include <math.h>

#define BB 32
#define LL 4096
#define CC 256
#define VV 5
#define THR 128
#define GXB 16          // blocks per batch for kstat & kbig (256 tokens each)

typedef unsigned long long u64t;

// ---------------- f32x2 packed helpers (Blackwell) ----------------
__device__ __forceinline__ u64t f2_pack(float lo, float hi) {
    u64t r; asm("mov.b64 %0, {%1, %2};" : "=l"(r) : "f"(lo), "f"(hi)); return r;
}
__device__ __forceinline__ void f2_unpack(u64t p, float& lo, float& hi) {
    asm("mov.b64 {%0, %1}, %2;" : "=f"(lo), "=f"(hi) : "l"(p));
}
__device__ __forceinline__ u64t f2_fma(u64t a, u64t b, u64t c) {
    u64t r; asm("fma.rn.f32x2 %0, %1, %2, %3;" : "=l"(r) : "l"(a), "l"(b), "l"(c)); return r;
}
__device__ __forceinline__ u64t f2_add(u64t a, u64t b) {
    u64t r; asm("add.rn.f32x2 %0, %1, %2;" : "=l"(r) : "l"(a), "l"(b)); return r;
}

// ---------------- device scratch ----------------
__device__ __align__(16) float g_base[BB * CC];
__device__ __align__(16) float g_A1[BB * VV * CC];    // sum_l a*rs*(f-m)
__device__ __align__(16) float g_A3[BB * VV];         // sum_l a
__device__ __align__(16) float g_projg[BB * VV * CC];
__device__ __align__(16) float g_sgp[BB * VV];
__device__ __align__(16) float g_sbp[BB * VV];
__device__ __align__(16) float g_MT[CC * CC];         // MT[e][c] = sum_k Wk[e,k]*Wq[c,k]
__device__ __align__(16) float4 g_mrs4[BB * LL / 2];  // (m0,rs0,m1,rs1) per token pair
__device__ unsigned g_cnt[BB];

// ---------------- kstat tail smem overlay (56 KB) ----------------
#define T_SL(sm)  ((float*)(sm))                 // [5][256]
#define T_X(sm)   ((float*)((sm) + 5120))        // [5][256]
#define T_P(sm)   ((float*)((sm) + 30720))       // [2][5][256]
#define T_PR(sm)  ((float*)((sm) + 51200))       // [5][256]
#define TAIL_BYTES 56320

// ---------------- kslot smem overlay (115 KB, 1024 threads) ----------------
#define KS_SL(sm)  ((float*)(sm))                // [5][256]   5120
#define KS_X(sm)   ((float*)((sm) + 5120))       // [5][256]
#define KS_U(sm)   ((float*)((sm) + 10240))      // [5][256]
#define KS_H(sm)   ((float*)((sm) + 15360))      // [5][256]
#define KS_HID(sm) ((float*)((sm) + 20480))      // [5][512]  10240
#define KS_P(sm)   ((float*)((sm) + 30720))      // up to [16][5][256] = 81920
#define KS_PR(sm)  ((float*)((sm) + 112640))     // [5][256]
#define KSLOT_BYTES 117760

// ---------------- 128-thread helpers (kstat tail only) ----------------
__device__ __forceinline__ void ln_rows128(const float* __restrict__ src,
                                           float* __restrict__ dst,
                                           const float* __restrict__ gc,
                                           const float* __restrict__ bc, int t) {
    int wid = t >> 5, lane = t & 31;
    for (int v = wid; v < VV; v += 4) {
        float x[8], s = 0.f, q = 0.f;
#pragma unroll
        for (int i = 0; i < 8; i++) {
            x[i] = src[v * CC + lane + 32 * i];
            s += x[i]; q += x[i] * x[i];
        }
#pragma unroll
        for (int off = 16; off; off >>= 1) {
            s += __shfl_xor_sync(0xffffffffu, s, off);
            q += __shfl_xor_sync(0xffffffffu, q, off);
        }
        float m = s * (1.0f / 256.0f);
        float rs = rsqrtf(q * (1.0f / 256.0f) - m * m + 1e-5f);
#pragma unroll
        for (int i = 0; i < 8; i++) {
            int c = lane + 32 * i;
            dst[v * CC + c] = (x[i] - m) * rs * gc[c] + bc[c];
        }
    }
}

// out 256, depth 256; 2-way k-split over 128 threads (kstat tail only)
__device__ __forceinline__ void gemm256_128(const float* __restrict__ sIn,
                                            const float* __restrict__ W,
                                            float* __restrict__ sP, int t) {
    int grp = t & 63, seg = t >> 6;
    const float4* Wp = (const float4*)W + seg * 128 * 64 + grp;
    const float* xin = sIn + seg * 128;
    float4 acc[VV];
#pragma unroll
    for (int v = 0; v < VV; v++) acc[v] = make_float4(0.f, 0.f, 0.f, 0.f);
#pragma unroll 8
    for (int k = 0; k < 128; k++) {
        float4 w = Wp[k * 64];
#pragma unroll
        for (int v = 0; v < VV; v++) {
            float xa = xin[v * CC + k];
            acc[v].x += xa * w.x; acc[v].y += xa * w.y;
            acc[v].z += xa * w.z; acc[v].w += xa * w.w;
        }
    }
#pragma unroll
    for (int v = 0; v < VV; v++)
        ((float4*)(sP + (seg * VV + v) * CC))[grp] = acc[v];
}

// kstat's LN(slots) -> projection (128 threads). Requires T_SL filled.
__device__ void ln_proj_tail128(char* sm, int t, int b,
                                const float* g_sl, const float* b_sl,
                                const float* g_in, const float* b_in, float scale) {
    float* sSl = T_SL(sm); float* sX = T_X(sm);
    float* sP = T_P(sm);   float* sPR = T_PR(sm);
    ln_rows128(sSl, sX, g_sl, b_sl, t);
    __syncthreads();
    gemm256_128(sX, g_MT, sP, t);
    __syncthreads();
    for (int idx = t; idx < VV * CC; idx += THR) {
        int v = idx >> 8, c = idx & 255;
        float pr = (sP[v * CC + c] + sP[(VV + v) * CC + c]) * scale;
        g_projg[b * VV * CC + idx] = g_in[c] * pr;
        sPR[idx] = pr;
    }
    __syncthreads();
    if (t < 10) {
        int v = t % 5;
        const float* coef = (t < 5) ? g_in : b_in;
        float s = 0.f;
#pragma unroll 8
        for (int c = 0; c < CC; c++) s += coef[c] * sPR[v * CC + c];
        if (t < 5) g_sgp[b * VV + v] = s; else g_sbp[b * VV + v] = s;
    }
}

// ---------------- km: MT = Wk @ Wq^T + zero all scratch ----------------
__global__ void __launch_bounds__(256) km(const float* __restrict__ Wq,
                                          const float* __restrict__ Wk) {
    __shared__ float As[32][33];
    __shared__ float Bs[32][33];
    int tx = threadIdx.x & 31, ty = threadIdx.x >> 5;
    int c0 = blockIdx.x * 32, e0 = blockIdx.y * 32;

    int flat = (blockIdx.y * 8 + blockIdx.x) * 256 + threadIdx.x;  // 0..16383
    for (int i = flat; i < BB * VV * CC; i += 16384) g_A1[i] = 0.f;
    if (flat < BB * CC) g_base[flat] = 0.f;
    if (flat < BB * VV) g_A3[flat] = 0.f;
    if (flat < BB) g_cnt[flat] = 0u;

    float acc[4] = {0.f, 0.f, 0.f, 0.f};
    for (int k0 = 0; k0 < CC; k0 += 32) {
#pragma unroll
        for (int j = 0; j < 4; j++) {
            As[ty + 8 * j][tx] = Wk[(e0 + ty + 8 * j) * CC + k0 + tx];
            Bs[ty + 8 * j][tx] = Wq[(c0 + ty + 8 * j) * CC + k0 + tx];
        }
        __syncthreads();
#pragma unroll
        for (int kk = 0; kk < 32; kk++) {
            float bq = Bs[tx][kk];
#pragma unroll
            for (int j = 0; j < 4; j++) acc[j] += As[ty + 8 * j][kk] * bq;
        }
        __syncthreads();
    }
#pragma unroll
    for (int j = 0; j < 4; j++)
        g_MT[(e0 + ty + 8 * j) * CC + c0 + tx] = acc[j];
}

// ---------------- kstat: per-token (m, rs) + g_base column sums; init tail ----------------
__global__ void __launch_bounds__(128) kstat(const float* __restrict__ F,
                                             const float* __restrict__ noise,
                                             float* __restrict__ slots,
                                             const float* __restrict__ g_in,
                                             const float* __restrict__ b_in,
                                             const float* __restrict__ g_sl,
                                             const float* __restrict__ b_sl,
                                             const float* __restrict__ scale_p,
                                             const float* __restrict__ ns_p) {
    extern __shared__ char sm[];
    __shared__ unsigned flg;
    int b = blockIdx.y, t = threadIdx.x;
    int w = t >> 5, lane = t & 31;
    int l0 = blockIdx.x * 256 + w * 64;
    const float4* base = (const float4*)(F + ((size_t)(b * LL + l0)) * CC);

    float cs[8] = {0.f, 0.f, 0.f, 0.f, 0.f, 0.f, 0.f, 0.f};

    for (int r = 0; r < 64; r += 2) {
        float4 fa0 = base[r * 64 + lane];
        float4 fb0 = base[r * 64 + 32 + lane];
        float4 fa1 = base[r * 64 + 64 + lane];
        float4 fb1 = base[r * 64 + 96 + lane];
        float s0 = (fa0.x + fa0.y) + (fa0.z + fa0.w) + (fb0.x + fb0.y) + (fb0.z + fb0.w);
        float q0 = fa0.x * fa0.x + fa0.y * fa0.y + fa0.z * fa0.z + fa0.w * fa0.w
                 + fb0.x * fb0.x + fb0.y * fb0.y + fb0.z * fb0.z + fb0.w * fb0.w;
        float s1 = (fa1.x + fa1.y) + (fa1.z + fa1.w) + (fb1.x + fb1.y) + (fb1.z + fb1.w);
        float q1 = fa1.x * fa1.x + fa1.y * fa1.y + fa1.z * fa1.z + fa1.w * fa1.w
                 + fb1.x * fb1.x + fb1.y * fb1.y + fb1.z * fb1.z + fb1.w * fb1.w;
        cs[0] += fa0.x + fa1.x; cs[1] += fa0.y + fa1.y;
        cs[2] += fa0.z + fa1.z; cs[3] += fa0.w + fa1.w;
        cs[4] += fb0.x + fb1.x; cs[5] += fb0.y + fb1.y;
        cs[6] += fb0.z + fb1.z; cs[7] += fb0.w + fb1.w;
#pragma unroll
        for (int off = 16; off; off >>= 1) {
            s0 += __shfl_xor_sync(0xffffffffu, s0, off);
            s1 += __shfl_xor_sync(0xffffffffu, s1, off);
            q0 += __shfl_xor_sync(0xffffffffu, q0, off);
            q1 += __shfl_xor_sync(0xffffffffu, q1, off);
        }
        float m0 = s0 * (1.0f / 256.0f);
        float m1 = s1 * (1.0f / 256.0f);
        float rs0 = rsqrtf(q0 * (1.0f / 256.0f) - m0 * m0 + 1e-5f);
        float rs1 = rsqrtf(q1 * (1.0f / 256.0f) - m1 * m1 + 1e-5f);
        if (lane == 0)
            g_mrs4[((size_t)b * LL + l0 + r) >> 1] = make_float4(m0, rs0, m1, rs1);
    }

    int cA = 4 * lane, cB = 128 + 4 * lane;
#pragma unroll
    for (int i = 0; i < 4; i++) {
        atomicAdd(&g_base[b * CC + cA + i], cs[i]);
        atomicAdd(&g_base[b * CC + cB + i], cs[4 + i]);
    }
    __threadfence();
    __syncthreads();   // ALL threads' atomics done+fenced before counter bump
    if (t == 0) flg = atomicAdd(&g_cnt[b], 1u);
    __syncthreads();
    if (flg != GXB - 1) return;

    // init slots = mean + noise*|ns|, then projection
    float* sSl = T_SL(sm);
    float ns = fabsf(ns_p[0]);
    for (int idx = t; idx < VV * CC; idx += THR) {
        int c = idx & 255;
        float sv = __ldcg(&g_base[b * CC + c]) * (1.0f / (float)LL)
                 + noise[b * VV * CC + idx] * ns;
        sSl[idx] = sv;
        slots[b * VV * CC + idx] = sv;
    }
    __syncthreads();
    ln_proj_tail128(sm, t, b, g_sl, b_sl, g_in, b_in, scale_p[0]);
    if (t == 0) g_cnt[b] = 0;
}

// ---------------- kbig: streaming pass, f32x2-packed FMAs ----------------
__global__ void __launch_bounds__(128) kbig(const float* __restrict__ F,
                                            float* __restrict__ attn,
                                            int write_attn) {
    int b = blockIdx.y, t = threadIdx.x;
    int w = t >> 5, lane = t & 31;
    int l0 = blockIdx.x * 256 + w * 64;
    int cA = 4 * lane, cB = 128 + 4 * lane;

    float sgp[VV], sbp[VV];
    u64t gpp[VV][4];                 // packed gp pairs: cols (cA,cA+1)(cA+2,cA+3)(cB..)(..)
#pragma unroll
    for (int v = 0; v < VV; v++) {
        sgp[v] = g_sgp[b * VV + v];
        sbp[v] = g_sbp[b * VV + v];
        const float* gpp_s = &g_projg[(b * VV + v) * CC];
        gpp[v][0] = f2_pack(gpp_s[cA + 0], gpp_s[cA + 1]);
        gpp[v][1] = f2_pack(gpp_s[cA + 2], gpp_s[cA + 3]);
        gpp[v][2] = f2_pack(gpp_s[cB + 0], gpp_s[cB + 1]);
        gpp[v][3] = f2_pack(gpp_s[cB + 2], gpp_s[cB + 3]);
    }
    u64t A1p[VV][4];
    float A3[VV];
#pragma unroll
    for (int v = 0; v < VV; v++) {
        A3[v] = 0.f;
#pragma unroll
        for (int j = 0; j < 4; j++) A1p[v][j] = 0ull;
    }

    const ulonglong2* base2 = (const ulonglong2*)(F + ((size_t)(b * LL + l0)) * CC);
    float* aout = attn + ((size_t)b * LL + l0) * VV;

    for (int r = 0; r < 64; r += 2) {
        ulonglong2 A0 = base2[r * 64 + lane];
        ulonglong2 B0 = base2[r * 64 + 32 + lane];
        ulonglong2 A1l = base2[r * 64 + 64 + lane];
        ulonglong2 B1l = base2[r * 64 + 96 + lane];
        u64t f0p[4] = {A0.x, A0.y, B0.x, B0.y};
        u64t f1p[4] = {A1l.x, A1l.y, B1l.x, B1l.y};

        u64t d0p[VV], d1p[VV];
#pragma unroll
        for (int v = 0; v < VV; v++) { d0p[v] = 0ull; d1p[v] = 0ull; }
#pragma unroll
        for (int j = 0; j < 4; j++) {
#pragma unroll
            for (int v = 0; v < VV; v++) {
                d0p[v] = f2_fma(f0p[j], gpp[v][j], d0p[v]);
                d1p[v] = f2_fma(f1p[j], gpp[v][j], d1p[v]);
            }
        }
        float d0[VV], d1[VV];
#pragma unroll
        for (int v = 0; v < VV; v++) {
            float lo, hi;
            f2_unpack(d0p[v], lo, hi); d0[v] = lo + hi;
            f2_unpack(d1p[v], lo, hi); d1[v] = lo + hi;
        }
#pragma unroll
        for (int off = 16; off; off >>= 1) {
#pragma unroll
            for (int v = 0; v < VV; v++) {
                d0[v] += __shfl_xor_sync(0xffffffffu, d0[v], off);
                d1[v] += __shfl_xor_sync(0xffffffffu, d1[v], off);
            }
        }
        float4 mr = g_mrs4[((size_t)b * LL + l0 + r) >> 1];
        float m0 = mr.x, rs0 = mr.y, m1 = mr.z, rs1 = mr.w;

        float lg0[VV], lg1[VV];
#pragma unroll
        for (int v = 0; v < VV; v++) {
            lg0[v] = rs0 * (d0[v] - m0 * sgp[v]) + sbp[v];
            lg1[v] = rs1 * (d1[v] - m1 * sgp[v]) + sbp[v];
        }
        float mx0 = lg0[0], mx1 = lg1[0];
#pragma unroll
        for (int v = 1; v < VV; v++) {
            mx0 = fmaxf(mx0, lg0[v]);
            mx1 = fmaxf(mx1, lg1[v]);
        }
        float e0[VV], e1[VV], se0 = 0.f, se1 = 0.f;
#pragma unroll
        for (int v = 0; v < VV; v++) {
            e0[v] = __expf(lg0[v] - mx0); se0 += e0[v];
            e1[v] = __expf(lg1[v] - mx1); se1 += e1[v];
        }
        float inv0 = 1.0f / se0, inv1 = 1.0f / se1;
        float a0[VV], a1v[VV];
#pragma unroll
        for (int v = 0; v < VV; v++) {
            a0[v] = e0[v] * inv0;
            a1v[v] = e1[v] * inv1;
        }

        // f -= m (packed), then A1 += (a*rs) * (f - m) (packed)
        u64t nm0 = f2_pack(-m0, -m0), nm1 = f2_pack(-m1, -m1);
#pragma unroll
        for (int j = 0; j < 4; j++) {
            f0p[j] = f2_add(f0p[j], nm0);
            f1p[j] = f2_add(f1p[j], nm1);
        }
#pragma unroll
        for (int v = 0; v < VV; v++) {
            float c0 = a0[v] * rs0, c1 = a1v[v] * rs1;
            u64t c0p = f2_pack(c0, c0), c1p = f2_pack(c1, c1);
            A3[v] += a0[v] + a1v[v];
#pragma unroll
            for (int j = 0; j < 4; j++) {
                A1p[v][j] = f2_fma(c0p, f0p[j], A1p[v][j]);
                A1p[v][j] = f2_fma(c1p, f1p[j], A1p[v][j]);
            }
        }

        if (write_attn) {
            if (lane < VV) {
                float av = lane == 0 ? a0[0] : lane == 1 ? a0[1] : lane == 2 ? a0[2]
                         : lane == 3 ? a0[3] : a0[4];
                aout[r * VV + lane] = av;
            } else if (lane < 2 * VV) {
                int j = lane - VV;
                float av = j == 0 ? a1v[0] : j == 1 ? a1v[1] : j == 2 ? a1v[2]
                         : j == 3 ? a1v[3] : a1v[4];
                aout[(r + 1) * VV + j] = av;
            }
        }
    }

    // flush block contributions (coalesced REDG per v-plane)
#pragma unroll
    for (int v = 0; v < VV; v++) {
#pragma unroll
        for (int j = 0; j < 4; j++) {
            int c = (j < 2) ? (cA + 2 * j) : (cB + 2 * (j - 2));
            float lo, hi;
            f2_unpack(A1p[v][j], lo, hi);
            atomicAdd(&g_A1[(b * VV + v) * CC + c], lo);
            atomicAdd(&g_A1[(b * VV + v) * CC + c + 1], hi);
        }
        if (lane == 0) atomicAdd(&g_A3[b * VV + v], A3[v]);
    }
}

// ---------------- knop: no-op spacer so ncu (-s 5) lands on kbig ----------------
__global__ void knop() {}

// ---------------- kslot: slot update, 1024 threads, deep k-split GEMMs ----------------
__global__ void __launch_bounds__(1024) kslot(float* __restrict__ slots,
                                              const float* __restrict__ g_in,
                                              const float* __restrict__ b_in,
                                              const float* __restrict__ g_sl,
                                              const float* __restrict__ b_sl,
                                              const float* __restrict__ g_up,
                                              const float* __restrict__ b_up,
                                              const float* __restrict__ Wv,
                                              const float* __restrict__ W1,
                                              const float* __restrict__ b1,
                                              const float* __restrict__ W2,
                                              const float* __restrict__ b2,
                                              const float* __restrict__ scale_p,
                                              int do_proj) {
    extern __shared__ char sm[];
    __shared__ float s_a3[VV];
    float* sSl = KS_SL(sm); float* sX = KS_X(sm); float* sU = KS_U(sm);
    float* sH = KS_H(sm);   float* sHid = KS_HID(sm);
    float* sP = KS_P(sm);   float* sPR = KS_PR(sm);

    int b = blockIdx.x, t = threadIdx.x;
    int wid = t >> 5, lane = t & 31;

    if (t < VV) { s_a3[t] = __ldcg(&g_A3[b * VV + t]); g_A3[b * VV + t] = 0.f; }
    for (int idx = t; idx < VV * CC; idx += 1024)
        sSl[idx] = slots[b * VV * CC + idx];
    __syncthreads();
    for (int idx = t; idx < VV * CC; idx += 1024) {
        int v = idx >> 8, c = idx & 255;
        float a1 = __ldcg(&g_A1[b * VV * CC + idx]);
        g_A1[b * VV * CC + idx] = 0.f;
        sX[idx] = g_in[c] * a1 + b_in[c] * s_a3[v];
    }
    __syncthreads();

    // ---- Wv GEMM: 64 f4-groups x 16 segs (depth 16) ----
    {
        int grp = t & 63, seg = t >> 6;
        const float4* Wp = (const float4*)Wv + (seg * 16) * 64 + grp;
        const float* xin = sX + seg * 16;
        float4 acc[VV];
#pragma unroll
        for (int v = 0; v < VV; v++) acc[v] = make_float4(0.f, 0.f, 0.f, 0.f);
#pragma unroll
        for (int k = 0; k < 16; k++) {
            float4 wv4 = Wp[k * 64];
#pragma unroll
            for (int v = 0; v < VV; v++) {
                float xa = xin[v * CC + k];
                acc[v].x += xa * wv4.x; acc[v].y += xa * wv4.y;
                acc[v].z += xa * wv4.z; acc[v].w += xa * wv4.w;
            }
        }
#pragma unroll
        for (int v = 0; v < VV; v++)
            ((float4*)(sP + (seg * VV + v) * CC))[grp] = acc[v];
    }
    __syncthreads();
    for (int idx = t; idx < VV * CC; idx += 1024) {
        int v = idx >> 8, c = idx & 255;
        float s = 0.f;
#pragma unroll
        for (int sg = 0; sg < 16; sg++) s += sP[(sg * VV + v) * CC + c];
        sU[idx] = s / (s_a3[v] + 1e-8f);
    }
    __syncthreads();

    // ---- LN(updates) -> sH (warps 0..4, one slot each) ----
    if (wid < VV) {
        float x[8], s = 0.f, q = 0.f;
#pragma unroll
        for (int i = 0; i < 8; i++) {
            x[i] = sU[wid * CC + lane + 32 * i];
            s += x[i]; q += x[i] * x[i];
        }
#pragma unroll
        for (int off = 16; off; off >>= 1) {
            s += __shfl_xor_sync(0xffffffffu, s, off);
            q += __shfl_xor_sync(0xffffffffu, q, off);
        }
        float m = s * (1.0f / 256.0f);
        float rs = rsqrtf(q * (1.0f / 256.0f) - m * m + 1e-5f);
#pragma unroll
        for (int i = 0; i < 8; i++) {
            int c = lane + 32 * i;
            sH[wid * CC + c] = (x[i] - m) * rs * g_up[c] + b_up[c];
        }
    }
    __syncthreads();

    // ---- W1 GEMM: 128 f4-groups x 8 segs (depth 32) ----
    {
        int grp = t & 127, seg = t >> 7;
        const float4* Wp = (const float4*)W1 + (seg * 32) * 128 + grp;
        const float* xin = sH + seg * 32;
        float4 acc[VV];
#pragma unroll
        for (int v = 0; v < VV; v++) acc[v] = make_float4(0.f, 0.f, 0.f, 0.f);
#pragma unroll 8
        for (int k = 0; k < 32; k++) {
            float4 wv4 = Wp[k * 128];
#pragma unroll
            for (int v = 0; v < VV; v++) {
                float xa = xin[v * CC + k];
                acc[v].x += xa * wv4.x; acc[v].y += xa * wv4.y;
                acc[v].z += xa * wv4.z; acc[v].w += xa * wv4.w;
            }
        }
#pragma unroll
        for (int v = 0; v < VV; v++)
            ((float4*)(sP + (seg * VV + v) * 512))[grp] = acc[v];
    }
    __syncthreads();
    for (int idx = t; idx < VV * 512; idx += 1024) {
        int v = idx >> 9, j = idx & 511;
        float h = b1[j];
#pragma unroll
        for (int sg = 0; sg < 8; sg++) h += sP[(sg * VV + v) * 512 + j];
        sHid[idx] = fmaxf(h, 0.f);
    }
    __syncthreads();

    // ---- W2 GEMM: 64 f4-groups x 16 segs (depth 32) ----
    {
        int grp = t & 63, seg = t >> 6;
        const float4* Wp = (const float4*)W2 + (seg * 32) * 64 + grp;
        const float* xin = sHid + seg * 32;
        float4 acc[VV];
#pragma unroll
        for (int v = 0; v < VV; v++) acc[v] = make_float4(0.f, 0.f, 0.f, 0.f);
#pragma unroll 8
        for (int k = 0; k < 32; k++) {
            float4 wv4 = Wp[k * 64];
#pragma unroll
            for (int v = 0; v < VV; v++) {
                float xa = xin[v * 512 + k];
                acc[v].x += xa * wv4.x; acc[v].y += xa * wv4.y;
                acc[v].z += xa * wv4.z; acc[v].w += xa * wv4.w;
            }
        }
#pragma unroll
        for (int v = 0; v < VV; v++)
            ((float4*)(sP + (seg * VV + v) * CC))[grp] = acc[v];
    }
    __syncthreads();
    for (int idx = t; idx < VV * CC; idx += 1024) {
        int v = idx >> 8, c = idx & 255;
        float d = b2[c];
#pragma unroll
        for (int sg = 0; sg < 16; sg++) d += sP[(sg * VV + v) * CC + c];
        float sn = sSl[idx] + d;
        sSl[idx] = sn;
        slots[b * VV * CC + idx] = sn;
    }
    __syncthreads();

    if (!do_proj) return;

    // ---- LN(slots) -> sX ----
    if (wid < VV) {
        float x[8], s = 0.f, q = 0.f;
#pragma unroll
        for (int i = 0; i < 8; i++) {
            x[i] = sSl[wid * CC + lane + 32 * i];
            s += x[i]; q += x[i] * x[i];
        }
#pragma unroll
        for (int off = 16; off; off >>= 1) {
            s += __shfl_xor_sync(0xffffffffu, s, off);
            q += __shfl_xor_sync(0xffffffffu, q, off);
        }
        float m = s * (1.0f / 256.0f);
        float rs = rsqrtf(q * (1.0f / 256.0f) - m * m + 1e-5f);
#pragma unroll
        for (int i = 0; i < 8; i++) {
            int c = lane + 32 * i;
            sX[wid * CC + c] = (x[i] - m) * rs * g_sl[c] + b_sl[c];
        }
    }
    __syncthreads();

    // ---- MT GEMM (same shape as Wv) ----
    {
        int grp = t & 63, seg = t >> 6;
        const float4* Wp = (const float4*)g_MT + (seg * 16) * 64 + grp;
        const float* xin = sX + seg * 16;
        float4 acc[VV];
#pragma unroll
        for (int v = 0; v < VV; v++) acc[v] = make_float4(0.f, 0.f, 0.f, 0.f);
#pragma unroll
        for (int k = 0; k < 16; k++) {
            float4 wv4 = Wp[k * 64];
#pragma unroll
            for (int v = 0; v < VV; v++) {
                float xa = xin[v * CC + k];
                acc[v].x += xa * wv4.x; acc[v].y += xa * wv4.y;
                acc[v].z += xa * wv4.z; acc[v].w += xa * wv4.w;
            }
        }
#pragma unroll
        for (int v = 0; v < VV; v++)
            ((float4*)(sP + (seg * VV + v) * CC))[grp] = acc[v];
    }
    __syncthreads();
    float sc = scale_p[0];
    for (int idx = t; idx < VV * CC; idx += 1024) {
        int v = idx >> 8, c = idx & 255;
        float s = 0.f;
#pragma unroll
        for (int sg = 0; sg < 16; sg++) s += sP[(sg * VV + v) * CC + c];
        float pr = s * sc;
        g_projg[b * VV * CC + idx] = g_in[c] * pr;
        sPR[idx] = pr;
    }
    __syncthreads();
    if (t < 10) {
        int v = t % 5;
        const float* coef = (t < 5) ? g_in : b_in;
        float s = 0.f;
#pragma unroll 8
        for (int c = 0; c < CC; c++) s += coef[c] * sPR[v * CC + c];
        if (t < 5) g_sgp[b * VV + v] = s; else g_sbp[b * VV + v] = s;
    }
}

// ---------------- host ----------------
extern "C" void kernel_launch(void* const* d_in, const int* in_sizes, int n_in,
                              void* d_out, int out_size) {
    const float* F     = (const float*)d_in[0];
    const float* noise = (const float*)d_in[1];
    const float* Wq    = (const float*)d_in[2];
    const float* Wk    = (const float*)d_in[3];
    const float* Wv    = (const float*)d_in[4];
    const float* scale = (const float*)d_in[5];
    const float* g_in  = (const float*)d_in[6];
    const float* b_in  = (const float*)d_in[7];
    const float* g_sl  = (const float*)d_in[8];
    const float* b_sl  = (const float*)d_in[9];
    const float* g_up  = (const float*)d_in[10];
    const float* b_up  = (const float*)d_in[11];
    const float* W1    = (const float*)d_in[12];
    const float* b1    = (const float*)d_in[13];
    const float* W2    = (const float*)d_in[14];
    const float* b2    = (const float*)d_in[15];
    const float* nsc   = (const float*)d_in[16];

    float* out       = (float*)d_out;
    float* slots_out = out;                    // [B,V,C]
    float* attn_out  = out + BB * VV * CC;     // [B,L,V]

    cudaFuncSetAttribute(kstat, cudaFuncAttributeMaxDynamicSharedMemorySize, TAIL_BYTES);
    cudaFuncSetAttribute(kslot, cudaFuncAttributeMaxDynamicSharedMemorySize, KSLOT_BYTES);

    km<<<dim3(8, 8), 256>>>(Wq, Wk);                                       // #1
    kstat<<<dim3(GXB, 32), THR, TAIL_BYTES>>>(F, noise, slots_out, g_in, b_in,
                                              g_sl, b_sl, scale, nsc);     // #2

    kbig<<<dim3(GXB, 32), THR>>>(F, attn_out, 0);                          // #3
    kslot<<<BB, 1024, KSLOT_BYTES>>>(slots_out, g_in, b_in, g_sl, b_sl, g_up, b_up,
                                     Wv, W1, b1, W2, b2, scale, 1);        // #4
    knop<<<1, 32>>>();                                                     // #5 spacer
    kbig<<<dim3(GXB, 32), THR>>>(F, attn_out, 0);                          // #6 <- profiled
    kslot<<<BB, 1024, KSLOT_BYTES>>>(slots_out, g_in, b_in, g_sl, b_sl, g_up, b_up,
                                     Wv, W1, b1, W2, b2, scale, 1);        // #7
    kbig<<<dim3(GXB, 32), THR>>>(F, attn_out, 1);                          // #8
    kslot<<<BB, 1024, KSLOT_BYTES>>>(slots_out, g_in, b_in, g_sl, b_sl, g_up, b_up,
                                     Wv, W1, b1, W2, b2, scale, 0);        // #9
}

// round 14
// speedup vs baseline: 1.2659x; 1.2104x over previous
#include <cuda_runtime.h>
#include <math.h>

#define BB 32
#define LL 4096
#define CC 256
#define VV 5
#define THR 128
#define GXB 16          // blocks per batch for kstat & kbig (256 tokens each)

typedef unsigned long long u64t;

// ---------------- f32x2 packed helpers (Blackwell) ----------------
__device__ __forceinline__ u64t f2_pack(float lo, float hi) {
    u64t r; asm("mov.b64 %0, {%1, %2};" : "=l"(r) : "f"(lo), "f"(hi)); return r;
}
__device__ __forceinline__ void f2_unpack(u64t p, float& lo, float& hi) {
    asm("mov.b64 {%0, %1}, %2;" : "=f"(lo), "=f"(hi) : "l"(p));
}
__device__ __forceinline__ u64t f2_fma(u64t a, u64t b, u64t c) {
    u64t r; asm("fma.rn.f32x2 %0, %1, %2, %3;" : "=l"(r) : "l"(a), "l"(b), "l"(c)); return r;
}
__device__ __forceinline__ u64t f2_add(u64t a, u64t b) {
    u64t r; asm("add.rn.f32x2 %0, %1, %2;" : "=l"(r) : "l"(a), "l"(b)); return r;
}

// ---------------- device scratch ----------------
__device__ __align__(16) float g_base[BB * CC];
__device__ __align__(16) float g_A1[BB * VV * CC];    // sum_l a*rs*(f-m)
__device__ __align__(16) float g_A3[BB * VV];         // sum_l a
__device__ __align__(16) float g_projg[BB * VV * CC];
__device__ __align__(16) float g_sgp[BB * VV];
__device__ __align__(16) float g_sbp[BB * VV];
__device__ __align__(16) float g_MT[CC * CC];         // MT[e][c] = sum_k Wk[e,k]*Wq[c,k]
__device__ __align__(16) float4 g_mrs4[BB * LL / 2];  // (m0,rs0,m1,rs1) per token pair
__device__ unsigned g_cnt[BB];

// ---------------- kstat tail smem overlay (56 KB) ----------------
#define T_SL(sm)  ((float*)(sm))                 // [5][256]
#define T_X(sm)   ((float*)((sm) + 5120))        // [5][256]
#define T_P(sm)   ((float*)((sm) + 30720))       // [2][5][256]
#define T_PR(sm)  ((float*)((sm) + 51200))       // [5][256]
#define TAIL_BYTES 56320

// ---------------- kslot smem overlay (115 KB, 1024 threads) ----------------
#define KS_SL(sm)  ((float*)(sm))                // [5][256]   5120
#define KS_X(sm)   ((float*)((sm) + 5120))       // [5][256]
#define KS_U(sm)   ((float*)((sm) + 10240))      // [5][256]
#define KS_H(sm)   ((float*)((sm) + 15360))      // [5][256]
#define KS_HID(sm) ((float*)((sm) + 20480))      // [5][512]  10240
#define KS_P(sm)   ((float*)((sm) + 30720))      // up to [16][5][256] = 81920
#define KS_PR(sm)  ((float*)((sm) + 112640))     // [5][256]
#define KSLOT_BYTES 117760

// ---------------- 128-thread helpers (kstat tail only) ----------------
__device__ __forceinline__ void ln_rows128(const float* __restrict__ src,
                                           float* __restrict__ dst,
                                           const float* __restrict__ gc,
                                           const float* __restrict__ bc, int t) {
    int wid = t >> 5, lane = t & 31;
    for (int v = wid; v < VV; v += 4) {
        float x[8], s = 0.f, q = 0.f;
#pragma unroll
        for (int i = 0; i < 8; i++) {
            x[i] = src[v * CC + lane + 32 * i];
            s += x[i]; q += x[i] * x[i];
        }
#pragma unroll
        for (int off = 16; off; off >>= 1) {
            s += __shfl_xor_sync(0xffffffffu, s, off);
            q += __shfl_xor_sync(0xffffffffu, q, off);
        }
        float m = s * (1.0f / 256.0f);
        float rs = rsqrtf(q * (1.0f / 256.0f) - m * m + 1e-5f);
#pragma unroll
        for (int i = 0; i < 8; i++) {
            int c = lane + 32 * i;
            dst[v * CC + c] = (x[i] - m) * rs * gc[c] + bc[c];
        }
    }
}

// out 256, depth 256; 2-way k-split over 128 threads (kstat tail only)
__device__ __forceinline__ void gemm256_128(const float* __restrict__ sIn,
                                            const float* __restrict__ W,
                                            float* __restrict__ sP, int t) {
    int grp = t & 63, seg = t >> 6;
    const float4* Wp = (const float4*)W + seg * 128 * 64 + grp;
    const float* xin = sIn + seg * 128;
    float4 acc[VV];
#pragma unroll
    for (int v = 0; v < VV; v++) acc[v] = make_float4(0.f, 0.f, 0.f, 0.f);
#pragma unroll 8
    for (int k = 0; k < 128; k++) {
        float4 w = Wp[k * 64];
#pragma unroll
        for (int v = 0; v < VV; v++) {
            float xa = xin[v * CC + k];
            acc[v].x += xa * w.x; acc[v].y += xa * w.y;
            acc[v].z += xa * w.z; acc[v].w += xa * w.w;
        }
    }
#pragma unroll
    for (int v = 0; v < VV; v++)
        ((float4*)(sP + (seg * VV + v) * CC))[grp] = acc[v];
}

// kstat's LN(slots) -> projection (128 threads). Requires T_SL filled.
__device__ void ln_proj_tail128(char* sm, int t, int b,
                                const float* g_sl, const float* b_sl,
                                const float* g_in, const float* b_in, float scale) {
    float* sSl = T_SL(sm); float* sX = T_X(sm);
    float* sP = T_P(sm);   float* sPR = T_PR(sm);
    ln_rows128(sSl, sX, g_sl, b_sl, t);
    __syncthreads();
    gemm256_128(sX, g_MT, sP, t);
    __syncthreads();
    for (int idx = t; idx < VV * CC; idx += THR) {
        int v = idx >> 8, c = idx & 255;
        float pr = (sP[v * CC + c] + sP[(VV + v) * CC + c]) * scale;
        g_projg[b * VV * CC + idx] = g_in[c] * pr;
        sPR[idx] = pr;
    }
    __syncthreads();
    if (t < 10) {
        int v = t % 5;
        const float* coef = (t < 5) ? g_in : b_in;
        float s = 0.f;
#pragma unroll 8
        for (int c = 0; c < CC; c++) s += coef[c] * sPR[v * CC + c];
        if (t < 5) g_sgp[b * VV + v] = s; else g_sbp[b * VV + v] = s;
    }
}

// ---------------- km: MT = Wk @ Wq^T + zero all scratch ----------------
__global__ void __launch_bounds__(256) km(const float* __restrict__ Wq,
                                          const float* __restrict__ Wk) {
    __shared__ float As[32][33];
    __shared__ float Bs[32][33];
    int tx = threadIdx.x & 31, ty = threadIdx.x >> 5;
    int c0 = blockIdx.x * 32, e0 = blockIdx.y * 32;

    int flat = (blockIdx.y * 8 + blockIdx.x) * 256 + threadIdx.x;  // 0..16383
    for (int i = flat; i < BB * VV * CC; i += 16384) g_A1[i] = 0.f;
    if (flat < BB * CC) g_base[flat] = 0.f;
    if (flat < BB * VV) g_A3[flat] = 0.f;
    if (flat < BB) g_cnt[flat] = 0u;

    float acc[4] = {0.f, 0.f, 0.f, 0.f};
    for (int k0 = 0; k0 < CC; k0 += 32) {
#pragma unroll
        for (int j = 0; j < 4; j++) {
            As[ty + 8 * j][tx] = Wk[(e0 + ty + 8 * j) * CC + k0 + tx];
            Bs[ty + 8 * j][tx] = Wq[(c0 + ty + 8 * j) * CC + k0 + tx];
        }
        __syncthreads();
#pragma unroll
        for (int kk = 0; kk < 32; kk++) {
            float bq = Bs[tx][kk];
#pragma unroll
            for (int j = 0; j < 4; j++) acc[j] += As[ty + 8 * j][kk] * bq;
        }
        __syncthreads();
    }
#pragma unroll
    for (int j = 0; j < 4; j++)
        g_MT[(e0 + ty + 8 * j) * CC + c0 + tx] = acc[j];
}

// ---------------- kstat: per-token (m, rs) + g_base column sums; init tail ----------------
__global__ void __launch_bounds__(128) kstat(const float* __restrict__ F,
                                             const float* __restrict__ noise,
                                             float* __restrict__ slots,
                                             const float* __restrict__ g_in,
                                             const float* __restrict__ b_in,
                                             const float* __restrict__ g_sl,
                                             const float* __restrict__ b_sl,
                                             const float* __restrict__ scale_p,
                                             const float* __restrict__ ns_p) {
    extern __shared__ char sm[];
    __shared__ unsigned flg;
    int b = blockIdx.y, t = threadIdx.x;
    int w = t >> 5, lane = t & 31;
    int l0 = blockIdx.x * 256 + w * 64;
    const float4* base = (const float4*)(F + ((size_t)(b * LL + l0)) * CC);

    float cs[8] = {0.f, 0.f, 0.f, 0.f, 0.f, 0.f, 0.f, 0.f};

    for (int r = 0; r < 64; r += 2) {
        float4 fa0 = base[r * 64 + lane];
        float4 fb0 = base[r * 64 + 32 + lane];
        float4 fa1 = base[r * 64 + 64 + lane];
        float4 fb1 = base[r * 64 + 96 + lane];
        float s0 = (fa0.x + fa0.y) + (fa0.z + fa0.w) + (fb0.x + fb0.y) + (fb0.z + fb0.w);
        float q0 = fa0.x * fa0.x + fa0.y * fa0.y + fa0.z * fa0.z + fa0.w * fa0.w
                 + fb0.x * fb0.x + fb0.y * fb0.y + fb0.z * fb0.z + fb0.w * fb0.w;
        float s1 = (fa1.x + fa1.y) + (fa1.z + fa1.w) + (fb1.x + fb1.y) + (fb1.z + fb1.w);
        float q1 = fa1.x * fa1.x + fa1.y * fa1.y + fa1.z * fa1.z + fa1.w * fa1.w
                 + fb1.x * fb1.x + fb1.y * fb1.y + fb1.z * fb1.z + fb1.w * fb1.w;
        cs[0] += fa0.x + fa1.x; cs[1] += fa0.y + fa1.y;
        cs[2] += fa0.z + fa1.z; cs[3] += fa0.w + fa1.w;
        cs[4] += fb0.x + fb1.x; cs[5] += fb0.y + fb1.y;
        cs[6] += fb0.z + fb1.z; cs[7] += fb0.w + fb1.w;
#pragma unroll
        for (int off = 16; off; off >>= 1) {
            s0 += __shfl_xor_sync(0xffffffffu, s0, off);
            s1 += __shfl_xor_sync(0xffffffffu, s1, off);
            q0 += __shfl_xor_sync(0xffffffffu, q0, off);
            q1 += __shfl_xor_sync(0xffffffffu, q1, off);
        }
        float m0 = s0 * (1.0f / 256.0f);
        float m1 = s1 * (1.0f / 256.0f);
        float rs0 = rsqrtf(q0 * (1.0f / 256.0f) - m0 * m0 + 1e-5f);
        float rs1 = rsqrtf(q1 * (1.0f / 256.0f) - m1 * m1 + 1e-5f);
        if (lane == 0)
            g_mrs4[((size_t)b * LL + l0 + r) >> 1] = make_float4(m0, rs0, m1, rs1);
    }

    int cA = 4 * lane, cB = 128 + 4 * lane;
#pragma unroll
    for (int i = 0; i < 4; i++) {
        atomicAdd(&g_base[b * CC + cA + i], cs[i]);
        atomicAdd(&g_base[b * CC + cB + i], cs[4 + i]);
    }
    __threadfence();
    __syncthreads();   // ALL threads' atomics done+fenced before counter bump
    if (t == 0) flg = atomicAdd(&g_cnt[b], 1u);
    __syncthreads();
    if (flg != GXB - 1) return;

    // init slots = mean + noise*|ns|, then projection
    float* sSl = T_SL(sm);
    float ns = fabsf(ns_p[0]);
    for (int idx = t; idx < VV * CC; idx += THR) {
        int c = idx & 255;
        float sv = __ldcg(&g_base[b * CC + c]) * (1.0f / (float)LL)
                 + noise[b * VV * CC + idx] * ns;
        sSl[idx] = sv;
        slots[b * VV * CC + idx] = sv;
    }
    __syncthreads();
    ln_proj_tail128(sm, t, b, g_sl, b_sl, g_in, b_in, scale_p[0]);
    if (t == 0) g_cnt[b] = 0;
}

// ---------------- kbig: streaming pass, f32x2 FMAs, smem gp, packed butterfly ----------------
__global__ void __launch_bounds__(128, 4) kbig(const float* __restrict__ F,
                                               float* __restrict__ attn,
                                               int write_attn) {
    __shared__ float sGP[VV * CC];   // projection coefficients, block-shared
    int b = blockIdx.y, t = threadIdx.x;
    int w = t >> 5, lane = t & 31;
    int l0 = blockIdx.x * 256 + w * 64;
    int cA = 4 * lane, cB = 128 + 4 * lane;

    // load projection into smem once per block
    {
        float4* d = (float4*)sGP;
        const float4* s4 = (const float4*)(g_projg + b * VV * CC);
        for (int i = t; i < VV * CC / 4; i += THR) d[i] = s4[i];
    }
    __syncthreads();

    float sgp[VV], sbp[VV];
#pragma unroll
    for (int v = 0; v < VV; v++) {
        sgp[v] = g_sgp[b * VV + v];
        sbp[v] = g_sbp[b * VV + v];
    }
    u64t A1p[VV][4];
    float A3[VV];
#pragma unroll
    for (int v = 0; v < VV; v++) {
        A3[v] = 0.f;
#pragma unroll
        for (int j = 0; j < 4; j++) A1p[v][j] = 0ull;
    }
    // per-lane column offsets of the 4 packed pairs
    int offs[4] = {cA, cA + 2, cB, cB + 2};

    const ulonglong2* base2 = (const ulonglong2*)(F + ((size_t)(b * LL + l0)) * CC);
    float* aout = attn + ((size_t)b * LL + l0) * VV;

    for (int r = 0; r < 64; r += 2) {
        ulonglong2 A0 = base2[r * 64 + lane];
        ulonglong2 B0 = base2[r * 64 + 32 + lane];
        ulonglong2 A1l = base2[r * 64 + 64 + lane];
        ulonglong2 B1l = base2[r * 64 + 96 + lane];
        u64t f0p[4] = {A0.x, A0.y, B0.x, B0.y};
        u64t f1p[4] = {A1l.x, A1l.y, B1l.x, B1l.y};

        u64t d0p[VV], d1p[VV];
#pragma unroll
        for (int v = 0; v < VV; v++) { d0p[v] = 0ull; d1p[v] = 0ull; }
#pragma unroll
        for (int j = 0; j < 4; j++) {
            int off = offs[j];
#pragma unroll
            for (int v = 0; v < VV; v++) {
                u64t g = *(const u64t*)&sGP[v * CC + off];
                d0p[v] = f2_fma(f0p[j], g, d0p[v]);
                d1p[v] = f2_fma(f1p[j], g, d1p[v]);
            }
        }
        // pair (d0,d1) per v into one u64; packed butterfly (2 SHFL + 1 FADD2/stage)
        u64t d01[VV];
#pragma unroll
        for (int v = 0; v < VV; v++) {
            float lo0, hi0, lo1, hi1;
            f2_unpack(d0p[v], lo0, hi0);
            f2_unpack(d1p[v], lo1, hi1);
            d01[v] = f2_pack(lo0 + hi0, lo1 + hi1);
        }
#pragma unroll
        for (int off = 16; off; off >>= 1) {
#pragma unroll
            for (int v = 0; v < VV; v++)
                d01[v] = f2_add(d01[v], __shfl_xor_sync(0xffffffffu, d01[v], off));
        }
        float d0[VV], d1[VV];
#pragma unroll
        for (int v = 0; v < VV; v++) f2_unpack(d01[v], d0[v], d1[v]);

        float4 mr = g_mrs4[((size_t)b * LL + l0 + r) >> 1];
        float m0 = mr.x, rs0 = mr.y, m1 = mr.z, rs1 = mr.w;

        float lg0[VV], lg1[VV];
#pragma unroll
        for (int v = 0; v < VV; v++) {
            lg0[v] = rs0 * (d0[v] - m0 * sgp[v]) + sbp[v];
            lg1[v] = rs1 * (d1[v] - m1 * sgp[v]) + sbp[v];
        }
        float mx0 = lg0[0], mx1 = lg1[0];
#pragma unroll
        for (int v = 1; v < VV; v++) {
            mx0 = fmaxf(mx0, lg0[v]);
            mx1 = fmaxf(mx1, lg1[v]);
        }
        float e0[VV], e1[VV], se0 = 0.f, se1 = 0.f;
#pragma unroll
        for (int v = 0; v < VV; v++) {
            e0[v] = __expf(lg0[v] - mx0); se0 += e0[v];
            e1[v] = __expf(lg1[v] - mx1); se1 += e1[v];
        }
        float inv0 = 1.0f / se0, inv1 = 1.0f / se1;
        float a0[VV], a1v[VV];
#pragma unroll
        for (int v = 0; v < VV; v++) {
            a0[v] = e0[v] * inv0;
            a1v[v] = e1[v] * inv1;
        }

        // f -= m (packed), then A1 += (a*rs) * (f - m) (packed)
        u64t nm0 = f2_pack(-m0, -m0), nm1 = f2_pack(-m1, -m1);
#pragma unroll
        for (int j = 0; j < 4; j++) {
            f0p[j] = f2_add(f0p[j], nm0);
            f1p[j] = f2_add(f1p[j], nm1);
        }
#pragma unroll
        for (int v = 0; v < VV; v++) {
            float c0 = a0[v] * rs0, c1 = a1v[v] * rs1;
            u64t c0p = f2_pack(c0, c0), c1p = f2_pack(c1, c1);
            A3[v] += a0[v] + a1v[v];
#pragma unroll
            for (int j = 0; j < 4; j++) {
                A1p[v][j] = f2_fma(c0p, f0p[j], A1p[v][j]);
                A1p[v][j] = f2_fma(c1p, f1p[j], A1p[v][j]);
            }
        }

        if (write_attn) {
            if (lane < VV) {
                float av = lane == 0 ? a0[0] : lane == 1 ? a0[1] : lane == 2 ? a0[2]
                         : lane == 3 ? a0[3] : a0[4];
                aout[r * VV + lane] = av;
            } else if (lane < 2 * VV) {
                int j = lane - VV;
                float av = j == 0 ? a1v[0] : j == 1 ? a1v[1] : j == 2 ? a1v[2]
                         : j == 3 ? a1v[3] : a1v[4];
                aout[(r + 1) * VV + j] = av;
            }
        }
    }

    // flush block contributions (coalesced REDG per v-plane)
#pragma unroll
    for (int v = 0; v < VV; v++) {
#pragma unroll
        for (int j = 0; j < 4; j++) {
            int c = offs[j];
            float lo, hi;
            f2_unpack(A1p[v][j], lo, hi);
            atomicAdd(&g_A1[(b * VV + v) * CC + c], lo);
            atomicAdd(&g_A1[(b * VV + v) * CC + c + 1], hi);
        }
        if (lane == 0) atomicAdd(&g_A3[b * VV + v], A3[v]);
    }
}

// ---------------- knop: no-op spacer so ncu (-s 5) lands on kbig ----------------
__global__ void knop() {}

// ---------------- kslot: slot update, 1024 threads, deep k-split GEMMs ----------------
__global__ void __launch_bounds__(1024) kslot(float* __restrict__ slots,
                                              const float* __restrict__ g_in,
                                              const float* __restrict__ b_in,
                                              const float* __restrict__ g_sl,
                                              const float* __restrict__ b_sl,
                                              const float* __restrict__ g_up,
                                              const float* __restrict__ b_up,
                                              const float* __restrict__ Wv,
                                              const float* __restrict__ W1,
                                              const float* __restrict__ b1,
                                              const float* __restrict__ W2,
                                              const float* __restrict__ b2,
                                              const float* __restrict__ scale_p,
                                              int do_proj) {
    extern __shared__ char sm[];
    __shared__ float s_a3[VV];
    float* sSl = KS_SL(sm); float* sX = KS_X(sm); float* sU = KS_U(sm);
    float* sH = KS_H(sm);   float* sHid = KS_HID(sm);
    float* sP = KS_P(sm);   float* sPR = KS_PR(sm);

    int b = blockIdx.x, t = threadIdx.x;
    int wid = t >> 5, lane = t & 31;

    if (t < VV) { s_a3[t] = __ldcg(&g_A3[b * VV + t]); g_A3[b * VV + t] = 0.f; }
    for (int idx = t; idx < VV * CC; idx += 1024)
        sSl[idx] = slots[b * VV * CC + idx];
    __syncthreads();
    for (int idx = t; idx < VV * CC; idx += 1024) {
        int v = idx >> 8, c = idx & 255;
        float a1 = __ldcg(&g_A1[b * VV * CC + idx]);
        g_A1[b * VV * CC + idx] = 0.f;
        sX[idx] = g_in[c] * a1 + b_in[c] * s_a3[v];
    }
    __syncthreads();

    // ---- Wv GEMM: 64 f4-groups x 16 segs (depth 16) ----
    {
        int grp = t & 63, seg = t >> 6;
        const float4* Wp = (const float4*)Wv + (seg * 16) * 64 + grp;
        const float* xin = sX + seg * 16;
        float4 acc[VV];
#pragma unroll
        for (int v = 0; v < VV; v++) acc[v] = make_float4(0.f, 0.f, 0.f, 0.f);
#pragma unroll
        for (int k = 0; k < 16; k++) {
            float4 wv4 = Wp[k * 64];
#pragma unroll
            for (int v = 0; v < VV; v++) {
                float xa = xin[v * CC + k];
                acc[v].x += xa * wv4.x; acc[v].y += xa * wv4.y;
                acc[v].z += xa * wv4.z; acc[v].w += xa * wv4.w;
            }
        }
#pragma unroll
        for (int v = 0; v < VV; v++)
            ((float4*)(sP + (seg * VV + v) * CC))[grp] = acc[v];
    }
    __syncthreads();
    for (int idx = t; idx < VV * CC; idx += 1024) {
        int v = idx >> 8, c = idx & 255;
        float s = 0.f;
#pragma unroll
        for (int sg = 0; sg < 16; sg++) s += sP[(sg * VV + v) * CC + c];
        sU[idx] = s / (s_a3[v] + 1e-8f);
    }
    __syncthreads();

    // ---- LN(updates) -> sH (warps 0..4, one slot each) ----
    if (wid < VV) {
        float x[8], s = 0.f, q = 0.f;
#pragma unroll
        for (int i = 0; i < 8; i++) {
            x[i] = sU[wid * CC + lane + 32 * i];
            s += x[i]; q += x[i] * x[i];
        }
#pragma unroll
        for (int off = 16; off; off >>= 1) {
            s += __shfl_xor_sync(0xffffffffu, s, off);
            q += __shfl_xor_sync(0xffffffffu, q, off);
        }
        float m = s * (1.0f / 256.0f);
        float rs = rsqrtf(q * (1.0f / 256.0f) - m * m + 1e-5f);
#pragma unroll
        for (int i = 0; i < 8; i++) {
            int c = lane + 32 * i;
            sH[wid * CC + c] = (x[i] - m) * rs * g_up[c] + b_up[c];
        }
    }
    __syncthreads();

    // ---- W1 GEMM: 128 f4-groups x 8 segs (depth 32) ----
    {
        int grp = t & 127, seg = t >> 7;
        const float4* Wp = (const float4*)W1 + (seg * 32) * 128 + grp;
        const float* xin = sH + seg * 32;
        float4 acc[VV];
#pragma unroll
        for (int v = 0; v < VV; v++) acc[v] = make_float4(0.f, 0.f, 0.f, 0.f);
#pragma unroll 8
        for (int k = 0; k < 32; k++) {
            float4 wv4 = Wp[k * 128];
#pragma unroll
            for (int v = 0; v < VV; v++) {
                float xa = xin[v * CC + k];
                acc[v].x += xa * wv4.x; acc[v].y += xa * wv4.y;
                acc[v].z += xa * wv4.z; acc[v].w += xa * wv4.w;
            }
        }
#pragma unroll
        for (int v = 0; v < VV; v++)
            ((float4*)(sP + (seg * VV + v) * 512))[grp] = acc[v];
    }
    __syncthreads();
    for (int idx = t; idx < VV * 512; idx += 1024) {
        int v = idx >> 9, j = idx & 511;
        float h = b1[j];
#pragma unroll
        for (int sg = 0; sg < 8; sg++) h += sP[(sg * VV + v) * 512 + j];
        sHid[idx] = fmaxf(h, 0.f);
    }
    __syncthreads();

    // ---- W2 GEMM: 64 f4-groups x 16 segs (depth 32) ----
    {
        int grp = t & 63, seg = t >> 6;
        const float4* Wp = (const float4*)W2 + (seg * 32) * 64 + grp;
        const float* xin = sHid + seg * 32;
        float4 acc[VV];
#pragma unroll
        for (int v = 0; v < VV; v++) acc[v] = make_float4(0.f, 0.f, 0.f, 0.f);
#pragma unroll 8
        for (int k = 0; k < 32; k++) {
            float4 wv4 = Wp[k * 64];
#pragma unroll
            for (int v = 0; v < VV; v++) {
                float xa = xin[v * 512 + k];
                acc[v].x += xa * wv4.x; acc[v].y += xa * wv4.y;
                acc[v].z += xa * wv4.z; acc[v].w += xa * wv4.w;
            }
        }
#pragma unroll
        for (int v = 0; v < VV; v++)
            ((float4*)(sP + (seg * VV + v) * CC))[grp] = acc[v];
    }
    __syncthreads();
    for (int idx = t; idx < VV * CC; idx += 1024) {
        int v = idx >> 8, c = idx & 255;
        float d = b2[c];
#pragma unroll
        for (int sg = 0; sg < 16; sg++) d += sP[(sg * VV + v) * CC + c];
        float sn = sSl[idx] + d;
        sSl[idx] = sn;
        slots[b * VV * CC + idx] = sn;
    }
    __syncthreads();

    if (!do_proj) return;

    // ---- LN(slots) -> sX ----
    if (wid < VV) {
        float x[8], s = 0.f, q = 0.f;
#pragma unroll
        for (int i = 0; i < 8; i++) {
            x[i] = sSl[wid * CC + lane + 32 * i];
            s += x[i]; q += x[i] * x[i];
        }
#pragma unroll
        for (int off = 16; off; off >>= 1) {
            s += __shfl_xor_sync(0xffffffffu, s, off);
            q += __shfl_xor_sync(0xffffffffu, q, off);
        }
        float m = s * (1.0f / 256.0f);
        float rs = rsqrtf(q * (1.0f / 256.0f) - m * m + 1e-5f);
#pragma unroll
        for (int i = 0; i < 8; i++) {
            int c = lane + 32 * i;
            sX[wid * CC + c] = (x[i] - m) * rs * g_sl[c] + b_sl[c];
        }
    }
    __syncthreads();

    // ---- MT GEMM (same shape as Wv) ----
    {
        int grp = t & 63, seg = t >> 6;
        const float4* Wp = (const float4*)g_MT + (seg * 16) * 64 + grp;
        const float* xin = sX + seg * 16;
        float4 acc[VV];
#pragma unroll
        for (int v = 0; v < VV; v++) acc[v] = make_float4(0.f, 0.f, 0.f, 0.f);
#pragma unroll
        for (int k = 0; k < 16; k++) {
            float4 wv4 = Wp[k * 64];
#pragma unroll
            for (int v = 0; v < VV; v++) {
                float xa = xin[v * CC + k];
                acc[v].x += xa * wv4.x; acc[v].y += xa * wv4.y;
                acc[v].z += xa * wv4.z; acc[v].w += xa * wv4.w;
            }
        }
#pragma unroll
        for (int v = 0; v < VV; v++)
            ((float4*)(sP + (seg * VV + v) * CC))[grp] = acc[v];
    }
    __syncthreads();
    float sc = scale_p[0];
    for (int idx = t; idx < VV * CC; idx += 1024) {
        int v = idx >> 8, c = idx & 255;
        float s = 0.f;
#pragma unroll
        for (int sg = 0; sg < 16; sg++) s += sP[(sg * VV + v) * CC + c];
        float pr = s * sc;
        g_projg[b * VV * CC + idx] = g_in[c] * pr;
        sPR[idx] = pr;
    }
    __syncthreads();
    if (t < 10) {
        int v = t % 5;
        const float* coef = (t < 5) ? g_in : b_in;
        float s = 0.f;
#pragma unroll 8
        for (int c = 0; c < CC; c++) s += coef[c] * sPR[v * CC + c];
        if (t < 5) g_sgp[b * VV + v] = s; else g_sbp[b * VV + v] = s;
    }
}

// ---------------- host ----------------
extern "C" void kernel_launch(void* const* d_in, const int* in_sizes, int n_in,
                              void* d_out, int out_size) {
    const float* F     = (const float*)d_in[0];
    const float* noise = (const float*)d_in[1];
    const float* Wq    = (const float*)d_in[2];
    const float* Wk    = (const float*)d_in[3];
    const float* Wv    = (const float*)d_in[4];
    const float* scale = (const float*)d_in[5];
    const float* g_in  = (const float*)d_in[6];
    const float* b_in  = (const float*)d_in[7];
    const float* g_sl  = (const float*)d_in[8];
    const float* b_sl  = (const float*)d_in[9];
    const float* g_up  = (const float*)d_in[10];
    const float* b_up  = (const float*)d_in[11];
    const float* W1    = (const float*)d_in[12];
    const float* b1    = (const float*)d_in[13];
    const float* W2    = (const float*)d_in[14];
    const float* b2    = (const float*)d_in[15];
    const float* nsc   = (const float*)d_in[16];

    float* out       = (float*)d_out;
    float* slots_out = out;                    // [B,V,C]
    float* attn_out  = out + BB * VV * CC;     // [B,L,V]

    cudaFuncSetAttribute(kstat, cudaFuncAttributeMaxDynamicSharedMemorySize, TAIL_BYTES);
    cudaFuncSetAttribute(kslot, cudaFuncAttributeMaxDynamicSharedMemorySize, KSLOT_BYTES);

    km<<<dim3(8, 8), 256>>>(Wq, Wk);                                       // #1
    kstat<<<dim3(GXB, 32), THR, TAIL_BYTES>>>(F, noise, slots_out, g_in, b_in,
                                              g_sl, b_sl, scale, nsc);     // #2

    kbig<<<dim3(GXB, 32), THR>>>(F, attn_out, 0);                          // #3
    kslot<<<BB, 1024, KSLOT_BYTES>>>(slots_out, g_in, b_in, g_sl, b_sl, g_up, b_up,
                                     Wv, W1, b1, W2, b2, scale, 1);        // #4
    knop<<<1, 32>>>();                                                     // #5 spacer
    kbig<<<dim3(GXB, 32), THR>>>(F, attn_out, 0);                          // #6 <- profiled
    kslot<<<BB, 1024, KSLOT_BYTES>>>(slots_out, g_in, b_in, g_sl, b_sl, g_up, b_up,
                                     Wv, W1, b1, W2, b2, scale, 1);        // #7
    kbig<<<dim3(GXB, 32), THR>>>(F, attn_out, 1);                          // #8
    kslot<<<BB, 1024, KSLOT_BYTES>>>(slots_out, g_in, b_in, g_sl, b_sl, g_up, b_up,
                                     Wv, W1, b1, W2, b2, scale, 0);        // #9
}

// round 15
// speedup vs baseline: 1.2668x; 1.0007x over previous
#include <cuda_runtime.h>
#include <math.h>

#define BB 32
#define LL 4096
#define CC 256
#define VV 5
#define THR 128
#define GXB 16          // blocks per batch for kstat & kbig (256 tokens each)

typedef unsigned long long u64t;

// ---------------- f32x2 packed helpers (Blackwell) ----------------
__device__ __forceinline__ u64t f2_pack(float lo, float hi) {
    u64t r; asm("mov.b64 %0, {%1, %2};" : "=l"(r) : "f"(lo), "f"(hi)); return r;
}
__device__ __forceinline__ void f2_unpack(u64t p, float& lo, float& hi) {
    asm("mov.b64 {%0, %1}, %2;" : "=f"(lo), "=f"(hi) : "l"(p));
}
__device__ __forceinline__ u64t f2_fma(u64t a, u64t b, u64t c) {
    u64t r; asm("fma.rn.f32x2 %0, %1, %2, %3;" : "=l"(r) : "l"(a), "l"(b), "l"(c)); return r;
}
__device__ __forceinline__ u64t f2_add(u64t a, u64t b) {
    u64t r; asm("add.rn.f32x2 %0, %1, %2;" : "=l"(r) : "l"(a), "l"(b)); return r;
}
__device__ __forceinline__ u64t f2_bcast(float x) {
    u64t r; asm("mov.b64 %0, {%1, %1};" : "=l"(r) : "f"(x)); return r;
}

// ---------------- device scratch ----------------
__device__ __align__(16) float g_base[BB * CC];
__device__ __align__(16) float g_A1[BB * VV * CC];    // sum_l a*rs*(f-m)
__device__ __align__(16) float g_A3[BB * VV];         // sum_l a
__device__ __align__(16) float g_projg[BB * VV * CC];
__device__ __align__(16) float g_sgp[BB * VV];
__device__ __align__(16) float g_sbp[BB * VV];
__device__ __align__(16) float g_MT[CC * CC];         // MT[e][c] = sum_k Wk[e,k]*Wq[c,k]
__device__ __align__(16) float4 g_mrs4[BB * LL / 2];  // (m0,rs0,m1,rs1) per token pair
__device__ unsigned g_cnt[BB];

// ---------------- kstat tail smem overlay (56 KB) ----------------
#define T_SL(sm)  ((float*)(sm))                 // [5][256]
#define T_X(sm)   ((float*)((sm) + 5120))        // [5][256]
#define T_P(sm)   ((float*)((sm) + 30720))       // [2][5][256]
#define T_PR(sm)  ((float*)((sm) + 51200))       // [5][256]
#define TAIL_BYTES 56320

// ---------------- kslot smem overlay (115 KB, 1024 threads) ----------------
#define KS_SL(sm)  ((float*)(sm))                // [5][256]   5120
#define KS_X(sm)   ((float*)((sm) + 5120))       // [5][256]
#define KS_U(sm)   ((float*)((sm) + 10240))      // [5][256]
#define KS_H(sm)   ((float*)((sm) + 15360))      // [5][256]
#define KS_HID(sm) ((float*)((sm) + 20480))      // [5][512]  10240
#define KS_P(sm)   ((float*)((sm) + 30720))      // up to [16][5][256] = 81920
#define KS_PR(sm)  ((float*)((sm) + 112640))     // [5][256]
#define KSLOT_BYTES 117760

// ---------------- 128-thread helpers (kstat tail only) ----------------
__device__ __forceinline__ void ln_rows128(const float* __restrict__ src,
                                           float* __restrict__ dst,
                                           const float* __restrict__ gc,
                                           const float* __restrict__ bc, int t) {
    int wid = t >> 5, lane = t & 31;
    for (int v = wid; v < VV; v += 4) {
        float x[8], s = 0.f, q = 0.f;
#pragma unroll
        for (int i = 0; i < 8; i++) {
            x[i] = src[v * CC + lane + 32 * i];
            s += x[i]; q += x[i] * x[i];
        }
#pragma unroll
        for (int off = 16; off; off >>= 1) {
            s += __shfl_xor_sync(0xffffffffu, s, off);
            q += __shfl_xor_sync(0xffffffffu, q, off);
        }
        float m = s * (1.0f / 256.0f);
        float rs = rsqrtf(q * (1.0f / 256.0f) - m * m + 1e-5f);
#pragma unroll
        for (int i = 0; i < 8; i++) {
            int c = lane + 32 * i;
            dst[v * CC + c] = (x[i] - m) * rs * gc[c] + bc[c];
        }
    }
}

// out 256, depth 256; 2-way k-split over 128 threads (kstat tail only)
__device__ __forceinline__ void gemm256_128(const float* __restrict__ sIn,
                                            const float* __restrict__ W,
                                            float* __restrict__ sP, int t) {
    int grp = t & 63, seg = t >> 6;
    const float4* Wp = (const float4*)W + seg * 128 * 64 + grp;
    const float* xin = sIn + seg * 128;
    float4 acc[VV];
#pragma unroll
    for (int v = 0; v < VV; v++) acc[v] = make_float4(0.f, 0.f, 0.f, 0.f);
#pragma unroll 8
    for (int k = 0; k < 128; k++) {
        float4 w = Wp[k * 64];
#pragma unroll
        for (int v = 0; v < VV; v++) {
            float xa = xin[v * CC + k];
            acc[v].x += xa * w.x; acc[v].y += xa * w.y;
            acc[v].z += xa * w.z; acc[v].w += xa * w.w;
        }
    }
#pragma unroll
    for (int v = 0; v < VV; v++)
        ((float4*)(sP + (seg * VV + v) * CC))[grp] = acc[v];
}

// kstat's LN(slots) -> projection (128 threads). Requires T_SL filled.
__device__ void ln_proj_tail128(char* sm, int t, int b,
                                const float* g_sl, const float* b_sl,
                                const float* g_in, const float* b_in, float scale) {
    float* sSl = T_SL(sm); float* sX = T_X(sm);
    float* sP = T_P(sm);   float* sPR = T_PR(sm);
    ln_rows128(sSl, sX, g_sl, b_sl, t);
    __syncthreads();
    gemm256_128(sX, g_MT, sP, t);
    __syncthreads();
    for (int idx = t; idx < VV * CC; idx += THR) {
        int v = idx >> 8, c = idx & 255;
        float pr = (sP[v * CC + c] + sP[(VV + v) * CC + c]) * scale;
        g_projg[b * VV * CC + idx] = g_in[c] * pr;
        sPR[idx] = pr;
    }
    __syncthreads();
    if (t < 10) {
        int v = t % 5;
        const float* coef = (t < 5) ? g_in : b_in;
        float s = 0.f;
#pragma unroll 8
        for (int c = 0; c < CC; c++) s += coef[c] * sPR[v * CC + c];
        if (t < 5) g_sgp[b * VV + v] = s; else g_sbp[b * VV + v] = s;
    }
}

// ---------------- km: MT = Wk @ Wq^T + zero all scratch ----------------
__global__ void __launch_bounds__(256) km(const float* __restrict__ Wq,
                                          const float* __restrict__ Wk) {
    __shared__ float As[32][33];
    __shared__ float Bs[32][33];
    int tx = threadIdx.x & 31, ty = threadIdx.x >> 5;
    int c0 = blockIdx.x * 32, e0 = blockIdx.y * 32;

    int flat = (blockIdx.y * 8 + blockIdx.x) * 256 + threadIdx.x;  // 0..16383
    for (int i = flat; i < BB * VV * CC; i += 16384) g_A1[i] = 0.f;
    if (flat < BB * CC) g_base[flat] = 0.f;
    if (flat < BB * VV) g_A3[flat] = 0.f;
    if (flat < BB) g_cnt[flat] = 0u;

    float acc[4] = {0.f, 0.f, 0.f, 0.f};
    for (int k0 = 0; k0 < CC; k0 += 32) {
#pragma unroll
        for (int j = 0; j < 4; j++) {
            As[ty + 8 * j][tx] = Wk[(e0 + ty + 8 * j) * CC + k0 + tx];
            Bs[ty + 8 * j][tx] = Wq[(c0 + ty + 8 * j) * CC + k0 + tx];
        }
        __syncthreads();
#pragma unroll
        for (int kk = 0; kk < 32; kk++) {
            float bq = Bs[tx][kk];
#pragma unroll
            for (int j = 0; j < 4; j++) acc[j] += As[ty + 8 * j][kk] * bq;
        }
        __syncthreads();
    }
#pragma unroll
    for (int j = 0; j < 4; j++)
        g_MT[(e0 + ty + 8 * j) * CC + c0 + tx] = acc[j];
}

// ---------------- kstat: per-token (m, rs) + g_base column sums; init tail ----------------
__global__ void __launch_bounds__(128) kstat(const float* __restrict__ F,
                                             const float* __restrict__ noise,
                                             float* __restrict__ slots,
                                             const float* __restrict__ g_in,
                                             const float* __restrict__ b_in,
                                             const float* __restrict__ g_sl,
                                             const float* __restrict__ b_sl,
                                             const float* __restrict__ scale_p,
                                             const float* __restrict__ ns_p) {
    extern __shared__ char sm[];
    __shared__ unsigned flg;
    int b = blockIdx.y, t = threadIdx.x;
    int w = t >> 5, lane = t & 31;
    int l0 = blockIdx.x * 256 + w * 64;
    const float4* base = (const float4*)(F + ((size_t)(b * LL + l0)) * CC);

    float cs[8] = {0.f, 0.f, 0.f, 0.f, 0.f, 0.f, 0.f, 0.f};

    for (int r = 0; r < 64; r += 2) {
        float4 fa0 = base[r * 64 + lane];
        float4 fb0 = base[r * 64 + 32 + lane];
        float4 fa1 = base[r * 64 + 64 + lane];
        float4 fb1 = base[r * 64 + 96 + lane];
        float s0 = (fa0.x + fa0.y) + (fa0.z + fa0.w) + (fb0.x + fb0.y) + (fb0.z + fb0.w);
        float q0 = fa0.x * fa0.x + fa0.y * fa0.y + fa0.z * fa0.z + fa0.w * fa0.w
                 + fb0.x * fb0.x + fb0.y * fb0.y + fb0.z * fb0.z + fb0.w * fb0.w;
        float s1 = (fa1.x + fa1.y) + (fa1.z + fa1.w) + (fb1.x + fb1.y) + (fb1.z + fb1.w);
        float q1 = fa1.x * fa1.x + fa1.y * fa1.y + fa1.z * fa1.z + fa1.w * fa1.w
                 + fb1.x * fb1.x + fb1.y * fb1.y + fb1.z * fb1.z + fb1.w * fb1.w;
        cs[0] += fa0.x + fa1.x; cs[1] += fa0.y + fa1.y;
        cs[2] += fa0.z + fa1.z; cs[3] += fa0.w + fa1.w;
        cs[4] += fb0.x + fb1.x; cs[5] += fb0.y + fb1.y;
        cs[6] += fb0.z + fb1.z; cs[7] += fb0.w + fb1.w;
#pragma unroll
        for (int off = 16; off; off >>= 1) {
            s0 += __shfl_xor_sync(0xffffffffu, s0, off);
            s1 += __shfl_xor_sync(0xffffffffu, s1, off);
            q0 += __shfl_xor_sync(0xffffffffu, q0, off);
            q1 += __shfl_xor_sync(0xffffffffu, q1, off);
        }
        float m0 = s0 * (1.0f / 256.0f);
        float m1 = s1 * (1.0f / 256.0f);
        float rs0 = rsqrtf(q0 * (1.0f / 256.0f) - m0 * m0 + 1e-5f);
        float rs1 = rsqrtf(q1 * (1.0f / 256.0f) - m1 * m1 + 1e-5f);
        if (lane == 0)
            g_mrs4[((size_t)b * LL + l0 + r) >> 1] = make_float4(m0, rs0, m1, rs1);
    }

    int cA = 4 * lane, cB = 128 + 4 * lane;
#pragma unroll
    for (int i = 0; i < 4; i++) {
        atomicAdd(&g_base[b * CC + cA + i], cs[i]);
        atomicAdd(&g_base[b * CC + cB + i], cs[4 + i]);
    }
    __threadfence();
    __syncthreads();   // ALL threads' atomics done+fenced before counter bump
    if (t == 0) flg = atomicAdd(&g_cnt[b], 1u);
    __syncthreads();
    if (flg != GXB - 1) return;

    // init slots = mean + noise*|ns|, then projection
    float* sSl = T_SL(sm);
    float ns = fabsf(ns_p[0]);
    for (int idx = t; idx < VV * CC; idx += THR) {
        int c = idx & 255;
        float sv = __ldcg(&g_base[b * CC + c]) * (1.0f / (float)LL)
                 + noise[b * VV * CC + idx] * ns;
        sSl[idx] = sv;
        slots[b * VV * CC + idx] = sv;
    }
    __syncthreads();
    ln_proj_tail128(sm, t, b, g_sl, b_sl, g_in, b_in, scale_p[0]);
    if (t == 0) g_cnt[b] = 0;
}

// ---------------- kbig: 4-token interleaved streaming pass ----------------
__global__ void __launch_bounds__(128, 4) kbig(const float* __restrict__ F,
                                               float* __restrict__ attn,
                                               int write_attn) {
    __shared__ float sGP[VV * CC];   // projection coefficients, block-shared
    __shared__ float sSc[2 * VV];
    int b = blockIdx.y, t = threadIdx.x;
    int w = t >> 5, lane = t & 31;
    int l0 = blockIdx.x * 256 + w * 64;
    int cA = 4 * lane, cB = 128 + 4 * lane;

    {
        float4* d = (float4*)sGP;
        const float4* s4 = (const float4*)(g_projg + b * VV * CC);
        for (int i = t; i < VV * CC / 4; i += THR) d[i] = s4[i];
        if (t < VV) { sSc[t] = g_sgp[b * VV + t]; sSc[VV + t] = g_sbp[b * VV + t]; }
    }
    __syncthreads();

    float sgp[VV], sbp[VV];
#pragma unroll
    for (int v = 0; v < VV; v++) { sgp[v] = sSc[v]; sbp[v] = sSc[VV + v]; }

    u64t A1p[VV][4];
    float A3[VV];
#pragma unroll
    for (int v = 0; v < VV; v++) {
        A3[v] = 0.f;
#pragma unroll
        for (int j = 0; j < 4; j++) A1p[v][j] = 0ull;
    }
    int offs[4] = {cA, cA + 2, cB, cB + 2};

    const ulonglong2* base2 = (const ulonglong2*)(F + ((size_t)(b * LL + l0)) * CC);
    float* aout = attn + ((size_t)b * LL + l0) * VV;

    for (int r = 0; r < 64; r += 4) {
        u64t f0p[4], f1p[4], f2p[4], f3p[4];
        {
            ulonglong2 x;
            x = base2[(r + 0) * 64 + lane];      f0p[0] = x.x; f0p[1] = x.y;
            x = base2[(r + 0) * 64 + 32 + lane]; f0p[2] = x.x; f0p[3] = x.y;
            x = base2[(r + 1) * 64 + lane];      f1p[0] = x.x; f1p[1] = x.y;
            x = base2[(r + 1) * 64 + 32 + lane]; f1p[2] = x.x; f1p[3] = x.y;
            x = base2[(r + 2) * 64 + lane];      f2p[0] = x.x; f2p[1] = x.y;
            x = base2[(r + 2) * 64 + 32 + lane]; f2p[2] = x.x; f2p[3] = x.y;
            x = base2[(r + 3) * 64 + lane];      f3p[0] = x.x; f3p[1] = x.y;
            x = base2[(r + 3) * 64 + 32 + lane]; f3p[2] = x.x; f3p[3] = x.y;
        }

        // d partials, folded per-v immediately (two packed butterfly vectors)
        u64t d01[VV], d23[VV];
#pragma unroll
        for (int v = 0; v < VV; v++) {
            u64t p0 = 0ull, p1 = 0ull, p2 = 0ull, p3 = 0ull;
#pragma unroll
            for (int j = 0; j < 4; j++) {
                u64t g = *(const u64t*)&sGP[v * CC + offs[j]];
                p0 = f2_fma(f0p[j], g, p0);
                p1 = f2_fma(f1p[j], g, p1);
                p2 = f2_fma(f2p[j], g, p2);
                p3 = f2_fma(f3p[j], g, p3);
            }
            float l0f, h0, l1, h1, l2, h2, l3, h3;
            f2_unpack(p0, l0f, h0); f2_unpack(p1, l1, h1);
            f2_unpack(p2, l2, h2); f2_unpack(p3, l3, h3);
            d01[v] = f2_pack(l0f + h0, l1 + h1);
            d23[v] = f2_pack(l2 + h2, l3 + h3);
        }
        // two independent packed butterflies, interleaved
#pragma unroll
        for (int off = 16; off; off >>= 1) {
#pragma unroll
            for (int v = 0; v < VV; v++) {
                d01[v] = f2_add(d01[v], __shfl_xor_sync(0xffffffffu, d01[v], off));
                d23[v] = f2_add(d23[v], __shfl_xor_sync(0xffffffffu, d23[v], off));
            }
        }
        float4 mr01 = g_mrs4[((size_t)b * LL + l0 + r) >> 1];
        float4 mr23 = g_mrs4[(((size_t)b * LL + l0 + r) >> 1) + 1];

        // ---- pair (r, r+1) ----
        {
            float d0[VV], d1[VV];
#pragma unroll
            for (int v = 0; v < VV; v++) f2_unpack(d01[v], d0[v], d1[v]);
            float m0 = mr01.x, rs0 = mr01.y, m1 = mr01.z, rs1 = mr01.w;
            float lg0[VV], lg1[VV];
#pragma unroll
            for (int v = 0; v < VV; v++) {
                lg0[v] = rs0 * (d0[v] - m0 * sgp[v]) + sbp[v];
                lg1[v] = rs1 * (d1[v] - m1 * sgp[v]) + sbp[v];
            }
            float mx0 = lg0[0], mx1 = lg1[0];
#pragma unroll
            for (int v = 1; v < VV; v++) {
                mx0 = fmaxf(mx0, lg0[v]);
                mx1 = fmaxf(mx1, lg1[v]);
            }
            float e0[VV], e1[VV], se0 = 0.f, se1 = 0.f;
#pragma unroll
            for (int v = 0; v < VV; v++) {
                e0[v] = __expf(lg0[v] - mx0); se0 += e0[v];
                e1[v] = __expf(lg1[v] - mx1); se1 += e1[v];
            }
            float inv0 = 1.0f / se0, inv1 = 1.0f / se1;
            float a0[VV], a1v[VV];
#pragma unroll
            for (int v = 0; v < VV; v++) {
                a0[v] = e0[v] * inv0;
                a1v[v] = e1[v] * inv1;
            }
            u64t nm0 = f2_pack(-m0, -m0), nm1 = f2_pack(-m1, -m1);
#pragma unroll
            for (int j = 0; j < 4; j++) {
                f0p[j] = f2_add(f0p[j], nm0);
                f1p[j] = f2_add(f1p[j], nm1);
            }
#pragma unroll
            for (int v = 0; v < VV; v++) {
                float c0 = a0[v] * rs0, c1 = a1v[v] * rs1;
                u64t c0p = f2_pack(c0, c0), c1p = f2_pack(c1, c1);
                A3[v] += a0[v] + a1v[v];
#pragma unroll
                for (int j = 0; j < 4; j++) {
                    A1p[v][j] = f2_fma(c0p, f0p[j], A1p[v][j]);
                    A1p[v][j] = f2_fma(c1p, f1p[j], A1p[v][j]);
                }
            }
            if (write_attn) {
                if (lane < VV) {
                    float av = lane == 0 ? a0[0] : lane == 1 ? a0[1] : lane == 2 ? a0[2]
                             : lane == 3 ? a0[3] : a0[4];
                    aout[r * VV + lane] = av;
                } else if (lane < 2 * VV) {
                    int j = lane - VV;
                    float av = j == 0 ? a1v[0] : j == 1 ? a1v[1] : j == 2 ? a1v[2]
                             : j == 3 ? a1v[3] : a1v[4];
                    aout[(r + 1) * VV + j] = av;
                }
            }
        }
        // ---- pair (r+2, r+3) ----
        {
            float d2[VV], d3[VV];
#pragma unroll
            for (int v = 0; v < VV; v++) f2_unpack(d23[v], d2[v], d3[v]);
            float m2 = mr23.x, rs2 = mr23.y, m3 = mr23.z, rs3 = mr23.w;
            float lg2[VV], lg3[VV];
#pragma unroll
            for (int v = 0; v < VV; v++) {
                lg2[v] = rs2 * (d2[v] - m2 * sgp[v]) + sbp[v];
                lg3[v] = rs3 * (d3[v] - m3 * sgp[v]) + sbp[v];
            }
            float mx2 = lg2[0], mx3 = lg3[0];
#pragma unroll
            for (int v = 1; v < VV; v++) {
                mx2 = fmaxf(mx2, lg2[v]);
                mx3 = fmaxf(mx3, lg3[v]);
            }
            float e2[VV], e3[VV], se2 = 0.f, se3 = 0.f;
#pragma unroll
            for (int v = 0; v < VV; v++) {
                e2[v] = __expf(lg2[v] - mx2); se2 += e2[v];
                e3[v] = __expf(lg3[v] - mx3); se3 += e3[v];
            }
            float inv2 = 1.0f / se2, inv3 = 1.0f / se3;
            float a2w[VV], a3w[VV];
#pragma unroll
            for (int v = 0; v < VV; v++) {
                a2w[v] = e2[v] * inv2;
                a3w[v] = e3[v] * inv3;
            }
            u64t nm2 = f2_pack(-m2, -m2), nm3 = f2_pack(-m3, -m3);
#pragma unroll
            for (int j = 0; j < 4; j++) {
                f2p[j] = f2_add(f2p[j], nm2);
                f3p[j] = f2_add(f3p[j], nm3);
            }
#pragma unroll
            for (int v = 0; v < VV; v++) {
                float c2 = a2w[v] * rs2, c3 = a3w[v] * rs3;
                u64t c2p = f2_pack(c2, c2), c3p = f2_pack(c3, c3);
                A3[v] += a2w[v] + a3w[v];
#pragma unroll
                for (int j = 0; j < 4; j++) {
                    A1p[v][j] = f2_fma(c2p, f2p[j], A1p[v][j]);
                    A1p[v][j] = f2_fma(c3p, f3p[j], A1p[v][j]);
                }
            }
            if (write_attn) {
                if (lane >= 10 && lane < 10 + VV) {
                    int j = lane - 10;
                    float av = j == 0 ? a2w[0] : j == 1 ? a2w[1] : j == 2 ? a2w[2]
                             : j == 3 ? a2w[3] : a2w[4];
                    aout[(r + 2) * VV + j] = av;
                } else if (lane >= 15 && lane < 15 + VV) {
                    int j = lane - 15;
                    float av = j == 0 ? a3w[0] : j == 1 ? a3w[1] : j == 2 ? a3w[2]
                             : j == 3 ? a3w[3] : a3w[4];
                    aout[(r + 3) * VV + j] = av;
                }
            }
        }
    }

    // flush block contributions (coalesced REDG per v-plane)
#pragma unroll
    for (int v = 0; v < VV; v++) {
#pragma unroll
        for (int j = 0; j < 4; j++) {
            int c = offs[j];
            float lo, hi;
            f2_unpack(A1p[v][j], lo, hi);
            atomicAdd(&g_A1[(b * VV + v) * CC + c], lo);
            atomicAdd(&g_A1[(b * VV + v) * CC + c + 1], hi);
        }
        if (lane == 0) atomicAdd(&g_A3[b * VV + v], A3[v]);
    }
}

// ---------------- knop: no-op spacer ----------------
__global__ void knop() {}

// ---------------- kslot: slot update, 1024 threads, f32x2 k-split GEMMs ----------------
__global__ void __launch_bounds__(1024) kslot(float* __restrict__ slots,
                                              const float* __restrict__ g_in,
                                              const float* __restrict__ b_in,
                                              const float* __restrict__ g_sl,
                                              const float* __restrict__ b_sl,
                                              const float* __restrict__ g_up,
                                              const float* __restrict__ b_up,
                                              const float* __restrict__ Wv,
                                              const float* __restrict__ W1,
                                              const float* __restrict__ b1,
                                              const float* __restrict__ W2,
                                              const float* __restrict__ b2,
                                              const float* __restrict__ scale_p,
                                              int do_proj) {
    extern __shared__ char sm[];
    __shared__ float s_a3[VV];
    float* sSl = KS_SL(sm); float* sX = KS_X(sm); float* sU = KS_U(sm);
    float* sH = KS_H(sm);   float* sHid = KS_HID(sm);
    float* sP = KS_P(sm);   float* sPR = KS_PR(sm);

    int b = blockIdx.x, t = threadIdx.x;
    int wid = t >> 5, lane = t & 31;

    if (t < VV) { s_a3[t] = __ldcg(&g_A3[b * VV + t]); g_A3[b * VV + t] = 0.f; }
    for (int idx = t; idx < VV * CC; idx += 1024)
        sSl[idx] = slots[b * VV * CC + idx];
    __syncthreads();
    for (int idx = t; idx < VV * CC; idx += 1024) {
        int v = idx >> 8, c = idx & 255;
        float a1 = __ldcg(&g_A1[b * VV * CC + idx]);
        g_A1[b * VV * CC + idx] = 0.f;
        sX[idx] = g_in[c] * a1 + b_in[c] * s_a3[v];
    }
    __syncthreads();

    // ---- Wv GEMM: 64 f4-groups x 16 segs (depth 16), f32x2 ----
    {
        int grp = t & 63, seg = t >> 6;
        const ulonglong2* Wp = (const ulonglong2*)Wv + (seg * 16) * 64 + grp;
        const float* xin = sX + seg * 16;
        u64t al[VV], ah[VV];
#pragma unroll
        for (int v = 0; v < VV; v++) { al[v] = 0ull; ah[v] = 0ull; }
#pragma unroll
        for (int k = 0; k < 16; k++) {
            ulonglong2 w2 = Wp[k * 64];
#pragma unroll
            for (int v = 0; v < VV; v++) {
                u64t xa2 = f2_bcast(xin[v * CC + k]);
                al[v] = f2_fma(xa2, w2.x, al[v]);
                ah[v] = f2_fma(xa2, w2.y, ah[v]);
            }
        }
#pragma unroll
        for (int v = 0; v < VV; v++) {
            float x0, x1, x2, x3;
            f2_unpack(al[v], x0, x1); f2_unpack(ah[v], x2, x3);
            ((float4*)(sP + (seg * VV + v) * CC))[grp] = make_float4(x0, x1, x2, x3);
        }
    }
    __syncthreads();
    for (int idx = t; idx < VV * CC; idx += 1024) {
        int v = idx >> 8, c = idx & 255;
        float s = 0.f;
#pragma unroll
        for (int sg = 0; sg < 16; sg++) s += sP[(sg * VV + v) * CC + c];
        sU[idx] = s / (s_a3[v] + 1e-8f);
    }
    __syncthreads();

    // ---- LN(updates) -> sH (warps 0..4, one slot each) ----
    if (wid < VV) {
        float x[8], s = 0.f, q = 0.f;
#pragma unroll
        for (int i = 0; i < 8; i++) {
            x[i] = sU[wid * CC + lane + 32 * i];
            s += x[i]; q += x[i] * x[i];
        }
#pragma unroll
        for (int off = 16; off; off >>= 1) {
            s += __shfl_xor_sync(0xffffffffu, s, off);
            q += __shfl_xor_sync(0xffffffffu, q, off);
        }
        float m = s * (1.0f / 256.0f);
        float rs = rsqrtf(q * (1.0f / 256.0f) - m * m + 1e-5f);
#pragma unroll
        for (int i = 0; i < 8; i++) {
            int c = lane + 32 * i;
            sH[wid * CC + c] = (x[i] - m) * rs * g_up[c] + b_up[c];
        }
    }
    __syncthreads();

    // ---- W1 GEMM: 128 f4-groups x 8 segs (depth 32), f32x2 ----
    {
        int grp = t & 127, seg = t >> 7;
        const ulonglong2* Wp = (const ulonglong2*)W1 + (seg * 32) * 128 + grp;
        const float* xin = sH + seg * 32;
        u64t al[VV], ah[VV];
#pragma unroll
        for (int v = 0; v < VV; v++) { al[v] = 0ull; ah[v] = 0ull; }
#pragma unroll 8
        for (int k = 0; k < 32; k++) {
            ulonglong2 w2 = Wp[k * 128];
#pragma unroll
            for (int v = 0; v < VV; v++) {
                u64t xa2 = f2_bcast(xin[v * CC + k]);
                al[v] = f2_fma(xa2, w2.x, al[v]);
                ah[v] = f2_fma(xa2, w2.y, ah[v]);
            }
        }
#pragma unroll
        for (int v = 0; v < VV; v++) {
            float x0, x1, x2, x3;
            f2_unpack(al[v], x0, x1); f2_unpack(ah[v], x2, x3);
            ((float4*)(sP + (seg * VV + v) * 512))[grp] = make_float4(x0, x1, x2, x3);
        }
    }
    __syncthreads();
    for (int idx = t; idx < VV * 512; idx += 1024) {
        int v = idx >> 9, j = idx & 511;
        float h = b1[j];
#pragma unroll
        for (int sg = 0; sg < 8; sg++) h += sP[(sg * VV + v) * 512 + j];
        sHid[idx] = fmaxf(h, 0.f);
    }
    __syncthreads();

    // ---- W2 GEMM: 64 f4-groups x 16 segs (depth 32), f32x2 ----
    {
        int grp = t & 63, seg = t >> 6;
        const ulonglong2* Wp = (const ulonglong2*)W2 + (seg * 32) * 64 + grp;
        const float* xin = sHid + seg * 32;
        u64t al[VV], ah[VV];
#pragma unroll
        for (int v = 0; v < VV; v++) { al[v] = 0ull; ah[v] = 0ull; }
#pragma unroll 8
        for (int k = 0; k < 32; k++) {
            ulonglong2 w2 = Wp[k * 64];
#pragma unroll
            for (int v = 0; v < VV; v++) {
                u64t xa2 = f2_bcast(xin[v * 512 + k]);
                al[v] = f2_fma(xa2, w2.x, al[v]);
                ah[v] = f2_fma(xa2, w2.y, ah[v]);
            }
        }
#pragma unroll
        for (int v = 0; v < VV; v++) {
            float x0, x1, x2, x3;
            f2_unpack(al[v], x0, x1); f2_unpack(ah[v], x2, x3);
            ((float4*)(sP + (seg * VV + v) * CC))[grp] = make_float4(x0, x1, x2, x3);
        }
    }
    __syncthreads();
    for (int idx = t; idx < VV * CC; idx += 1024) {
        int v = idx >> 8, c = idx & 255;
        float d = b2[c];
#pragma unroll
        for (int sg = 0; sg < 16; sg++) d += sP[(sg * VV + v) * CC + c];
        float sn = sSl[idx] + d;
        sSl[idx] = sn;
        slots[b * VV * CC + idx] = sn;
    }
    __syncthreads();

    if (!do_proj) return;

    // ---- LN(slots) -> sX ----
    if (wid < VV) {
        float x[8], s = 0.f, q = 0.f;
#pragma unroll
        for (int i = 0; i < 8; i++) {
            x[i] = sSl[wid * CC + lane + 32 * i];
            s += x[i]; q += x[i] * x[i];
        }
#pragma unroll
        for (int off = 16; off; off >>= 1) {
            s += __shfl_xor_sync(0xffffffffu, s, off);
            q += __shfl_xor_sync(0xffffffffu, q, off);
        }
        float m = s * (1.0f / 256.0f);
        float rs = rsqrtf(q * (1.0f / 256.0f) - m * m + 1e-5f);
#pragma unroll
        for (int i = 0; i < 8; i++) {
            int c = lane + 32 * i;
            sX[wid * CC + c] = (x[i] - m) * rs * g_sl[c] + b_sl[c];
        }
    }
    __syncthreads();

    // ---- MT GEMM (same shape as Wv), f32x2 ----
    {
        int grp = t & 63, seg = t >> 6;
        const ulonglong2* Wp = (const ulonglong2*)g_MT + (seg * 16) * 64 + grp;
        const float* xin = sX + seg * 16;
        u64t al[VV], ah[VV];
#pragma unroll
        for (int v = 0; v < VV; v++) { al[v] = 0ull; ah[v] = 0ull; }
#pragma unroll
        for (int k = 0; k < 16; k++) {
            ulonglong2 w2 = Wp[k * 64];
#pragma unroll
            for (int v = 0; v < VV; v++) {
                u64t xa2 = f2_bcast(xin[v * CC + k]);
                al[v] = f2_fma(xa2, w2.x, al[v]);
                ah[v] = f2_fma(xa2, w2.y, ah[v]);
            }
        }
#pragma unroll
        for (int v = 0; v < VV; v++) {
            float x0, x1, x2, x3;
            f2_unpack(al[v], x0, x1); f2_unpack(ah[v], x2, x3);
            ((float4*)(sP + (seg * VV + v) * CC))[grp] = make_float4(x0, x1, x2, x3);
        }
    }
    __syncthreads();
    float sc = scale_p[0];
    for (int idx = t; idx < VV * CC; idx += 1024) {
        int v = idx >> 8, c = idx & 255;
        float s = 0.f;
#pragma unroll
        for (int sg = 0; sg < 16; sg++) s += sP[(sg * VV + v) * CC + c];
        float pr = s * sc;
        g_projg[b * VV * CC + idx] = g_in[c] * pr;
        sPR[idx] = pr;
    }
    __syncthreads();
    if (t < 10) {
        int v = t % 5;
        const float* coef = (t < 5) ? g_in : b_in;
        float s = 0.f;
#pragma unroll 8
        for (int c = 0; c < CC; c++) s += coef[c] * sPR[v * CC + c];
        if (t < 5) g_sgp[b * VV + v] = s; else g_sbp[b * VV + v] = s;
    }
}

// ---------------- host ----------------
extern "C" void kernel_launch(void* const* d_in, const int* in_sizes, int n_in,
                              void* d_out, int out_size) {
    const float* F     = (const float*)d_in[0];
    const float* noise = (const float*)d_in[1];
    const float* Wq    = (const float*)d_in[2];
    const float* Wk    = (const float*)d_in[3];
    const float* Wv    = (const float*)d_in[4];
    const float* scale = (const float*)d_in[5];
    const float* g_in  = (const float*)d_in[6];
    const float* b_in  = (const float*)d_in[7];
    const float* g_sl  = (const float*)d_in[8];
    const float* b_sl  = (const float*)d_in[9];
    const float* g_up  = (const float*)d_in[10];
    const float* b_up  = (const float*)d_in[11];
    const float* W1    = (const float*)d_in[12];
    const float* b1    = (const float*)d_in[13];
    const float* W2    = (const float*)d_in[14];
    const float* b2    = (const float*)d_in[15];
    const float* nsc   = (const float*)d_in[16];

    float* out       = (float*)d_out;
    float* slots_out = out;                    // [B,V,C]
    float* attn_out  = out + BB * VV * CC;     // [B,L,V]

    cudaFuncSetAttribute(kstat, cudaFuncAttributeMaxDynamicSharedMemorySize, TAIL_BYTES);
    cudaFuncSetAttribute(kslot, cudaFuncAttributeMaxDynamicSharedMemorySize, KSLOT_BYTES);

    km<<<dim3(8, 8), 256>>>(Wq, Wk);                                       // #1
    kstat<<<dim3(GXB, 32), THR, TAIL_BYTES>>>(F, noise, slots_out, g_in, b_in,
                                              g_sl, b_sl, scale, nsc);     // #2

    kbig<<<dim3(GXB, 32), THR>>>(F, attn_out, 0);                          // #3
    kslot<<<BB, 1024, KSLOT_BYTES>>>(slots_out, g_in, b_in, g_sl, b_sl, g_up, b_up,
                                     Wv, W1, b1, W2, b2, scale, 1);        // #4
    knop<<<1, 32>>>();                                                     // #5 spacer
    kbig<<<dim3(GXB, 32), THR>>>(F, attn_out, 0);                          // #6
    kslot<<<BB, 1024, KSLOT_BYTES>>>(slots_out, g_in, b_in, g_sl, b_sl, g_up, b_up,
                                     Wv, W1, b1, W2, b2, scale, 1);        // #7
    kbig<<<dim3(GXB, 32), THR>>>(F, attn_out, 1);                          // #8
    kslot<<<BB, 1024, KSLOT_BYTES>>>(slots_out, g_in, b_in, g_sl, b_sl, g_up, b_up,
                                     Wv, W1, b1, W2, b2, scale, 0);        // #9
}